// round 3
// baseline (speedup 1.0000x reference)
#include <cuda_runtime.h>
#include <math.h>

// ---------------------------------------------------------------------------
// FEMBA forward: patch-embed -> posembed -> bidirectional Mamba -> LN ->
// 31x31 decoder conv -> stride-matched convT ; out = [rec | x]
// Shapes: B=8, C=64, T=4096; E=64, G0=32, G1=256; DM=2048, DIN=4096,
// DS=16, DC=4, DTR=128; tokens = 8*256 = 2048.
// ---------------------------------------------------------------------------

#define TOKS 2048
#define LSEQ 256
#define DM   2048
#define DIN  4096
#define DS   16
#define DTR  128
#define XZW  16384   // 2 dirs * 2*DIN
#define NMASK (8 * 64 * 4096)

// ---------------- scratch (device globals; no runtime allocation) ----------
__device__ float g_h   [TOKS * DM];            //  16 MB  current hidden (b,g1,dm)
__device__ float g_h2  [TOKS * DM];            //  16 MB  post-LN hidden
__device__ float g_xz  [(size_t)TOKS * XZW];   // 134 MB  in_proj output (both dirs)
__device__ float g_u   [2][TOKS * DIN];        //  67 MB  conv+silu output per dir
__device__ float g_xdbl[2][TOKS * 160];        //   3 MB  x_proj output per dir
__device__ float g_dt  [2][TOKS * DIN];        //  67 MB  softplus(dt) per dir
__device__ float g_y   [2][TOKS * DIN];        //  67 MB  gated scan output per dir
__device__ float g_o   [TOKS * DM];            //  16 MB  out_proj (sum of dirs)
__device__ float g_d   [TOKS * DM];            //  16 MB  decoder conv output
__device__ unsigned char g_mask[NMASK];        //   2 MB  canonical 0/1 mask
__device__ int g_mask_mode;                    //   0 = bytes, 1 = 32-bit words

__device__ __forceinline__ float siluf(float x) {
    return x / (1.f + __expf(-x));
}

// ---------------- 0) mask dtype sniff + normalize --------------------------
// The harness converts the JAX bool mask to one of {uint8, int32, float32}.
// Bytes at offset i%4==1 within the first NMASK bytes are ~50% nonzero for a
// uint8 mask but always zero for int32 0/1 (01 00 00 00) and f32 0.0/1.0
// (00 00 80 3F). Count them -> mode flag. Safe: only first NMASK bytes read.
__global__ void mask_detect_kernel(const unsigned char* __restrict__ m) {
    __shared__ int cnt;
    if (threadIdx.x == 0) cnt = 0;
    __syncthreads();
    int local = 0;
    for (int i = threadIdx.x * 4 + 1; i < 65536; i += 1024)
        if (m[i]) local++;
    atomicAdd(&cnt, local);
    __syncthreads();
    if (threadIdx.x == 0) g_mask_mode = (cnt > 0) ? 0 : 1;
}

__global__ void mask_norm_kernel(const void* __restrict__ m) {
    int i = blockIdx.x * 256 + threadIdx.x;
    if (i >= NMASK) return;
    if (g_mask_mode == 0)
        g_mask[i] = ((const unsigned char*)m)[i] ? 1 : 0;
    else
        g_mask[i] = (((const unsigned int*)m)[i] != 0u) ? 1 : 0;
}

// ---------------- 1) patch embed + pos embed -------------------------------
// h[b, g1, e*32+g0] = proj_b[e] + pos[g1, ch] + sum_{i<2,j<16} xm * W[e,i,j]
__global__ void patch_kernel(const float* __restrict__ x,
                             const float* __restrict__ pw,
                             const float* __restrict__ pb,
                             const float* __restrict__ pos) {
    int g1 = blockIdx.x, b = blockIdx.y, tid = threadIdx.x;
    __shared__ float sIn[64 * 16];   // rows 0..63 of the 16-wide column strip
    __shared__ float sW [64 * 32];   // proj_w (E=64, 2*16)
    for (int i = tid; i < 1024; i += 256) {
        int r = i >> 4, c = i & 15;
        size_t gi = (size_t)b * 64 * 4096 + (size_t)r * 4096 + g1 * 16 + c;
        float v = x[gi];
        if (g_mask[gi]) v = 0.f;
        sIn[i] = v;
    }
    for (int i = tid; i < 2048; i += 256) sW[i] = pw[i];
    __syncthreads();
    size_t ob = (size_t)(b * 256 + g1) * 2048;
    #pragma unroll
    for (int rep = 0; rep < 8; rep++) {
        int ch = tid + rep * 256;
        int e = ch >> 5, g0 = ch & 31;
        float acc = pb[e] + pos[g1 * 2048 + ch];
        const float* w   = &sW[e * 32];
        const float* in0 = &sIn[(2 * g0) * 16];
        #pragma unroll
        for (int j = 0; j < 32; j++) acc = fmaf(in0[j], w[j], acc);
        g_h[ob + ch] = acc;
    }
}

// ---------------- generic SGEMM: C[M,N] = A[M,K] @ B[N,K]^T ----------------
// EPI: 0 = store, 1 = softplus(acc + bias[n]), 2 = accumulate (+=)
// Requires M%128==0, K%8==0, 16B-aligned rows (all call sites satisfy).
template <int EPI>
__global__ void __launch_bounds__(256)
sgemm(const float* __restrict__ A, int lda,
      const float* __restrict__ B, int ldb,
      float* __restrict__ C, int ldc,
      int M, int N, int K, const float* __restrict__ bias) {
    __shared__ float As[8][128];
    __shared__ float Bs[8][128];
    int tid = threadIdx.x;
    int bm = blockIdx.y * 128, bn = blockIdx.x * 128;
    int lr = tid >> 1, lk = (tid & 1) * 4;
    int ty = tid >> 4, tx = tid & 15;
    float acc[8][8] = {};
    const float* Ap = A + (size_t)(bm + lr) * lda + lk;
    const float* Bp = B + (size_t)(bn + lr) * ldb + lk;
    bool bvalid = (bn + lr) < N;
    for (int k0 = 0; k0 < K; k0 += 8) {
        float4 av = *(const float4*)(Ap + k0);
        float4 bv = bvalid ? *(const float4*)(Bp + k0) : make_float4(0.f, 0.f, 0.f, 0.f);
        __syncthreads();
        As[lk + 0][lr] = av.x; As[lk + 1][lr] = av.y;
        As[lk + 2][lr] = av.z; As[lk + 3][lr] = av.w;
        Bs[lk + 0][lr] = bv.x; Bs[lk + 1][lr] = bv.y;
        Bs[lk + 2][lr] = bv.z; Bs[lk + 3][lr] = bv.w;
        __syncthreads();
        #pragma unroll
        for (int k = 0; k < 8; k++) {
            float a[8], bb[8];
            *(float4*)&a[0]  = *(const float4*)&As[k][ty * 8];
            *(float4*)&a[4]  = *(const float4*)&As[k][ty * 8 + 4];
            *(float4*)&bb[0] = *(const float4*)&Bs[k][tx * 8];
            *(float4*)&bb[4] = *(const float4*)&Bs[k][tx * 8 + 4];
            #pragma unroll
            for (int i = 0; i < 8; i++)
                #pragma unroll
                for (int j = 0; j < 8; j++)
                    acc[i][j] = fmaf(a[i], bb[j], acc[i][j]);
        }
    }
    #pragma unroll
    for (int i = 0; i < 8; i++) {
        int row = bm + ty * 8 + i;
        float* Cr = C + (size_t)row * ldc + bn + tx * 8;
        #pragma unroll
        for (int j = 0; j < 8; j++) {
            int col = bn + tx * 8 + j;
            if (col < N) {
                float v = acc[i][j];
                if (EPI == 1) {
                    v += bias[col];
                    v = (v > 20.f) ? v : log1pf(expf(v));
                }
                if (EPI == 2) v += Cr[j];
                Cr[j] = v;
            }
        }
    }
}

// ---------------- 2) causal/anticausal depthwise conv (DC=4) + silu --------
// dir 0: u[l] = silu(b + w0*x[l-3]+w1*x[l-2]+w2*x[l-1]+w3*x[l])
// dir 1 (flip folded in): u[l] = silu(b + w3*x[l]+w2*x[l+1]+w1*x[l+2]+w0*x[l+3])
__global__ void conv_silu_kernel(const float* __restrict__ cw,
                                 const float* __restrict__ cb) {
    int d = blockIdx.x * 256 + threadIdx.x;
    int b = blockIdx.y, dir = blockIdx.z;
    float w0 = cw[(dir * DIN + d) * 4 + 0];
    float w1 = cw[(dir * DIN + d) * 4 + 1];
    float w2 = cw[(dir * DIN + d) * 4 + 2];
    float w3 = cw[(dir * DIN + d) * 4 + 3];
    float bias = cb[dir * DIN + d];
    const float* src = g_xz + (size_t)(b * LSEQ) * XZW + dir * 8192 + d;
    float* dst = g_u[dir] + (size_t)(b * LSEQ) * DIN + d;
    float x1 = 0.f, x2 = 0.f, x3 = 0.f;
    if (dir == 0) {
        for (int l = 0; l < LSEQ; l++) {
            float x0 = src[(size_t)l * XZW];
            float v = bias + w0 * x3 + w1 * x2 + w2 * x1 + w3 * x0;
            dst[(size_t)l * DIN] = siluf(v);
            x3 = x2; x2 = x1; x1 = x0;
        }
    } else {
        for (int l = LSEQ - 1; l >= 0; l--) {
            float x0 = src[(size_t)l * XZW];
            float v = bias + w3 * x0 + w2 * x1 + w1 * x2 + w0 * x3;
            dst[(size_t)l * DIN] = siluf(v);
            x3 = x2; x2 = x1; x1 = x0;
        }
    }
}

// ---------------- 3) selective scan + gating -------------------------------
// Per (b,d): state[16]; fwd iterates l ascending, rev descending (flip folded).
// y = (scan + u*Dp) * silu(z)
__global__ void scan_kernel(const float* __restrict__ A_log,
                            const float* __restrict__ Dp) {
    int d = blockIdx.x * 256 + threadIdx.x;
    int b = blockIdx.y, dir = blockIdx.z;
    __shared__ float sBC[32];
    float Aa[16];
    #pragma unroll
    for (int s = 0; s < 16; s++)
        Aa[s] = -expf(A_log[(size_t)(dir * DIN + d) * 16 + s]);
    float dpv = Dp[dir * DIN + d];
    const float* dtp = g_dt[dir] + d;
    const float* up  = g_u[dir] + d;
    const float* xdp = g_xdbl[dir];
    const float* zp  = g_xz + (size_t)dir * 8192 + 4096 + d;
    float* yp = g_y[dir] + d;
    float st[16];
    #pragma unroll
    for (int s = 0; s < 16; s++) st[s] = 0.f;
    for (int step = 0; step < LSEQ; step++) {
        int l = dir ? (LSEQ - 1 - step) : step;
        size_t t = (size_t)b * LSEQ + l;
        __syncthreads();
        if (threadIdx.x < 32) sBC[threadIdx.x] = xdp[t * 160 + 128 + threadIdx.x];
        __syncthreads();
        float dtv = dtp[t * DIN];
        float uv  = up[t * DIN];
        float zv  = zp[t * XZW];
        float du  = dtv * uv;
        float accv = 0.f;
        #pragma unroll
        for (int s = 0; s < 16; s++) {
            float dA = __expf(dtv * Aa[s]);
            st[s] = fmaf(st[s], dA, du * sBC[s]);
            accv = fmaf(st[s], sBC[16 + s], accv);
        }
        yp[t * DIN] = (accv + uv * dpv) * siluf(zv);
    }
}

// ---------------- 4) residual add + LayerNorm ------------------------------
__global__ void addln_kernel(const float* __restrict__ g,
                             const float* __restrict__ be) {
    int t = blockIdx.x, tid = threadIdx.x;
    size_t base = (size_t)t * DM;
    float v[8], s = 0.f, s2 = 0.f;
    #pragma unroll
    for (int i = 0; i < 8; i++) {
        int idx = tid + i * 256;
        float val = g_h[base + idx] + g_o[base + idx];
        v[i] = val; s += val; s2 += val * val;
    }
    __shared__ float rs[8], rs2[8];
    #pragma unroll
    for (int off = 16; off; off >>= 1) {
        s  += __shfl_xor_sync(0xffffffffu, s,  off);
        s2 += __shfl_xor_sync(0xffffffffu, s2, off);
    }
    if ((tid & 31) == 0) { rs[tid >> 5] = s; rs2[tid >> 5] = s2; }
    __syncthreads();
    float S = 0.f, S2 = 0.f;
    #pragma unroll
    for (int i = 0; i < 8; i++) { S += rs[i]; S2 += rs2[i]; }
    float mean = S * (1.f / 2048.f);
    float var  = S2 * (1.f / 2048.f) - mean * mean;
    float rinv = rsqrtf(var + 1e-5f);
    #pragma unroll
    for (int i = 0; i < 8; i++) {
        int idx = tid + i * 256;
        g_h2[base + idx] = (v[i] - mean) * rinv * g[idx] + be[idx];
    }
}

// ---------------- 5) 31x31 SAME conv over (256 x 2048) image ---------------
__global__ void decconv_kernel(const float* __restrict__ kw) {
    __shared__ float sIn[62 * 62];
    __shared__ float sW[961];
    int w0 = blockIdx.x * 32, h0 = blockIdx.y * 32, b = blockIdx.z;
    int tid = threadIdx.x;
    for (int i = tid; i < 62 * 62; i += 256) {
        int r = i / 62, c = i % 62;
        int gh = h0 - 15 + r, gw = w0 - 15 + c;
        float v = 0.f;
        if (gh >= 0 && gh < 256 && gw >= 0 && gw < 2048)
            v = g_h2[(size_t)(b * 256 + gh) * 2048 + gw];
        sIn[i] = v;
    }
    for (int i = tid; i < 961; i += 256) sW[i] = kw[i];
    __syncthreads();
    int tx = tid & 31, tyb = tid >> 5;
    float acc[4] = {0.f, 0.f, 0.f, 0.f};
    for (int ky = 0; ky < 31; ky++) {
        #pragma unroll
        for (int kx = 0; kx < 31; kx++) {
            float w = sW[ky * 31 + kx];
            #pragma unroll
            for (int i = 0; i < 4; i++)
                acc[i] = fmaf(sIn[(tyb + 8 * i + ky) * 62 + tx + kx], w, acc[i]);
        }
    }
    #pragma unroll
    for (int i = 0; i < 4; i++) {
        int hh = h0 + tyb + 8 * i;
        g_d[(size_t)(b * 256 + hh) * 2048 + w0 + tx] = acc[i];
    }
}

// ---------------- 6) convT (kernel==stride => non-overlapping scatter) -----
// rec[b, 2g0+i, 16g1+j] = bT + sum_c d[b, g1, c*32+g0] * Wt[c, i, j]
__global__ void rec_kernel(const float* __restrict__ wt,
                           const float* __restrict__ wb,
                           float* __restrict__ out) {
    __shared__ float sW[2048];
    for (int i = threadIdx.x; i < 2048; i += 256) sW[i] = wt[i];
    __syncthreads();
    int idx = blockIdx.x * 256 + threadIdx.x;
    int ww = idx & 4095;
    int hh = (idx >> 12) & 63;
    int b  = idx >> 18;
    int g0 = hh >> 1, ii = hh & 1, g1 = ww >> 4, jj = ww & 15;
    const float* dp = g_d + (size_t)(b * 256 + g1) * 2048 + g0;
    float acc = wb[0];
    #pragma unroll 8
    for (int c = 0; c < 64; c++)
        acc = fmaf(dp[c * 32], sW[c * 32 + ii * 16 + jj], acc);
    out[idx] = acc;
}

// ---------------------------------------------------------------------------
extern "C" void kernel_launch(void* const* d_in, const int* in_sizes, int n_in,
                              void* d_out, int out_size) {
    const float* x          = (const float*)d_in[0];
    const void*  mk         = d_in[1];
    const float* proj_w     = (const float*)d_in[2];
    const float* proj_b     = (const float*)d_in[3];
    const float* pos_embed  = (const float*)d_in[4];
    const float* in_proj_w  = (const float*)d_in[5];
    const float* conv_w     = (const float*)d_in[6];
    const float* conv_b     = (const float*)d_in[7];
    const float* x_proj_w   = (const float*)d_in[8];
    const float* dt_proj_w  = (const float*)d_in[9];
    const float* dt_proj_b  = (const float*)d_in[10];
    const float* A_log      = (const float*)d_in[11];
    const float* Dp         = (const float*)d_in[12];
    const float* out_proj_w = (const float*)d_in[13];
    const float* ln_g       = (const float*)d_in[14];
    const float* ln_b       = (const float*)d_in[15];
    const float* dec_conv_w = (const float*)d_in[16];
    const float* convT_w    = (const float*)d_in[17];
    const float* convT_b    = (const float*)d_in[18];
    float* out = (float*)d_out;

    float *p_h, *p_xz, *p_u, *p_xdbl, *p_dt, *p_y, *p_o;
    cudaGetSymbolAddress((void**)&p_h,    g_h);
    cudaGetSymbolAddress((void**)&p_xz,   g_xz);
    cudaGetSymbolAddress((void**)&p_u,    g_u);
    cudaGetSymbolAddress((void**)&p_xdbl, g_xdbl);
    cudaGetSymbolAddress((void**)&p_dt,   g_dt);
    cudaGetSymbolAddress((void**)&p_y,    g_y);
    cudaGetSymbolAddress((void**)&p_o,    g_o);

    // 0) mask dtype detection + normalization -> g_mask
    mask_detect_kernel<<<1, 256>>>((const unsigned char*)mk);
    mask_norm_kernel<<<NMASK / 256, 256>>>(mk);

    // 1) patch embed + pos embed -> g_h (2048 tokens x 2048)
    patch_kernel<<<dim3(256, 8), 256>>>(x, proj_w, proj_b, pos_embed);

    // 2) fused in_proj for BOTH directions: (2048 x 2048) @ (16384 x 2048)^T
    sgemm<0><<<dim3(16384 / 128, TOKS / 128), 256>>>(
        p_h, DM, in_proj_w, DM, p_xz, XZW, TOKS, XZW, DM, nullptr);

    // 3) depthwise conv + silu, both directions -> g_u
    conv_silu_kernel<<<dim3(16, 8, 2), 256>>>(conv_w, conv_b);

    // 4) x_proj and dt_proj per direction
    for (int dir = 0; dir < 2; dir++) {
        sgemm<0><<<dim3(2, TOKS / 128), 256>>>(
            p_u + (size_t)dir * TOKS * DIN, DIN,
            x_proj_w + (size_t)dir * 160 * DIN, DIN,
            p_xdbl + (size_t)dir * TOKS * 160, 160,
            TOKS, 160, DIN, nullptr);
        sgemm<1><<<dim3(DIN / 128, TOKS / 128), 256>>>(
            p_xdbl + (size_t)dir * TOKS * 160, 160,
            dt_proj_w + (size_t)dir * DIN * DTR, DTR,
            p_dt + (size_t)dir * TOKS * DIN, DIN,
            TOKS, DIN, DTR, dt_proj_b + dir * DIN);
    }

    // 5) selective scan + gating, both directions -> g_y
    scan_kernel<<<dim3(16, 8, 2), 256>>>(A_log, Dp);

    // 6) out_proj: o = y0 @ W0^T + y1 @ W1^T
    sgemm<0><<<dim3(DM / 128, TOKS / 128), 256>>>(
        p_y, DIN, out_proj_w, DIN, p_o, DM, TOKS, DM, DIN, nullptr);
    sgemm<2><<<dim3(DM / 128, TOKS / 128), 256>>>(
        p_y + (size_t)TOKS * DIN, DIN,
        out_proj_w + (size_t)DM * DIN, DIN, p_o, DM, TOKS, DM, DIN, nullptr);

    // 7) residual + LayerNorm -> g_h2
    addln_kernel<<<TOKS, 256>>>(ln_g, ln_b);

    // 8) 31x31 decoder conv -> g_d
    decconv_kernel<<<dim3(64, 8, 8), 256>>>(dec_conv_w);

    // 9) convT reconstruction -> out[0 : 2097152]
    rec_kernel<<<8192, 256>>>(convT_w, convT_b, out);

    // 10) second tuple element: pass-through x
    if (out_size >= 2 * 2097152) {
        cudaMemcpyAsync(out + 2097152, x, (size_t)2097152 * sizeof(float),
                        cudaMemcpyDeviceToDevice, 0);
    }
}

// round 5
// speedup vs baseline: 1.6727x; 1.6727x over previous
#include <cuda_runtime.h>
#include <cuda_bf16.h>
#include <math.h>
#include <stdint.h>

// ---------------------------------------------------------------------------
// FEMBA forward. Big GEMMs (in_proj, out_proj) on mma.sync bf16 with 2-way
// split (3 products) for fp32-level accuracy. compute_100-safe (no tcgen05).
// ---------------------------------------------------------------------------

#define TOKS 2048
#define LSEQ 256
#define DM   2048
#define DIN  4096
#define DS   16
#define DTR  128
#define XZW  16384
#define NMASK (8 * 64 * 4096)

typedef __nv_bfloat16 bf16;

// ---------------- scratch (device globals) ----------------------------------
__device__ float g_h   [TOKS * DM];
__device__ bf16  g_hhi [TOKS * DM];
__device__ bf16  g_hlo [TOKS * DM];
__device__ float g_h2  [TOKS * DM];
__device__ float g_xz  [(size_t)TOKS * XZW];
__device__ float g_u   [2][TOKS * DIN];
__device__ float g_xdbl[2][TOKS * 160];
__device__ float g_dt  [2][TOKS * DIN];
__device__ bf16  g_yhi [2][TOKS * DIN];
__device__ bf16  g_ylo [2][TOKS * DIN];
__device__ float g_o   [TOKS * DM];
__device__ float g_d   [TOKS * DM];
__device__ bf16  g_inwhi[(size_t)XZW * DM];
__device__ bf16  g_inwlo[(size_t)XZW * DM];
__device__ bf16  g_outwhi[(size_t)2 * DM * DIN];
__device__ bf16  g_outwlo[(size_t)2 * DM * DIN];
__device__ unsigned char g_mask[NMASK];
__device__ int g_mask_mode;

__device__ __forceinline__ float siluf(float x) { return x / (1.f + __expf(-x)); }

__device__ __forceinline__ uint32_t smem_u32(const void* p) {
    uint32_t a;
    asm("{ .reg .u64 t; cvta.to.shared.u64 t, %1; cvt.u32.u64 %0, t; }" : "=r"(a) : "l"(p));
    return a;
}
__device__ __forceinline__ void cpa16(uint32_t dst, const void* src) {
    asm volatile("cp.async.cg.shared.global [%0], [%1], 16;" :: "r"(dst), "l"(src));
}
__device__ __forceinline__ void ldsm4(uint32_t addr, uint32_t* r) {
    asm volatile("ldmatrix.sync.aligned.m8n8.x4.shared.b16 {%0,%1,%2,%3}, [%4];"
                 : "=r"(r[0]), "=r"(r[1]), "=r"(r[2]), "=r"(r[3]) : "r"(addr));
}
__device__ __forceinline__ void mma_bf16(float* c, const uint32_t* a,
                                         uint32_t b0, uint32_t b1) {
    asm volatile("mma.sync.aligned.m16n8k16.row.col.f32.bf16.bf16.f32 "
                 "{%0,%1,%2,%3}, {%4,%5,%6,%7}, {%8,%9}, {%0,%1,%2,%3};"
                 : "+f"(c[0]), "+f"(c[1]), "+f"(c[2]), "+f"(c[3])
                 : "r"(a[0]), "r"(a[1]), "r"(a[2]), "r"(a[3]), "r"(b0), "r"(b1));
}

// ---------------- 0) mask dtype sniff + normalize ---------------------------
__global__ void mask_detect_kernel(const unsigned char* __restrict__ m) {
    __shared__ int cnt;
    if (threadIdx.x == 0) cnt = 0;
    __syncthreads();
    int local = 0;
    for (int i = threadIdx.x * 4 + 1; i < 65536; i += 1024)
        if (m[i]) local++;
    atomicAdd(&cnt, local);
    __syncthreads();
    if (threadIdx.x == 0) g_mask_mode = (cnt > 0) ? 0 : 1;
}
__global__ void mask_norm_kernel(const void* __restrict__ m) {
    int i = blockIdx.x * 256 + threadIdx.x;
    if (i >= NMASK) return;
    if (g_mask_mode == 0) g_mask[i] = ((const unsigned char*)m)[i] ? 1 : 0;
    else                  g_mask[i] = (((const unsigned int*)m)[i] != 0u) ? 1 : 0;
}

// ---------------- split: hi/lo bf16 decomposition ---------------------------
__global__ void split_kernel(const float* __restrict__ src, bf16* __restrict__ hi,
                             bf16* __restrict__ lo, int n) {
    for (int i = blockIdx.x * 256 + threadIdx.x; i < n; i += gridDim.x * 256) {
        float a = src[i];
        bf16 h = __float2bfloat16_rn(a);
        hi[i] = h;
        lo[i] = __float2bfloat16_rn(a - __bfloat162float(h));
    }
}

// ---------------- 1) patch embed + pos embed (emits h fp32 + hi/lo bf16) ----
__global__ void patch_kernel(const float* __restrict__ x,
                             const float* __restrict__ pw,
                             const float* __restrict__ pb,
                             const float* __restrict__ pos) {
    int g1 = blockIdx.x, b = blockIdx.y, tid = threadIdx.x;
    __shared__ float sIn[64 * 16];
    __shared__ float sW [64 * 32];
    for (int i = tid; i < 1024; i += 256) {
        int r = i >> 4, c = i & 15;
        size_t gi = (size_t)b * 64 * 4096 + (size_t)r * 4096 + g1 * 16 + c;
        float v = x[gi];
        if (g_mask[gi]) v = 0.f;
        sIn[i] = v;
    }
    for (int i = tid; i < 2048; i += 256) sW[i] = pw[i];
    __syncthreads();
    size_t ob = (size_t)(b * 256 + g1) * 2048;
    #pragma unroll
    for (int rep = 0; rep < 8; rep++) {
        int ch = tid + rep * 256;
        int e = ch >> 5, g0 = ch & 31;
        float acc = pb[e] + pos[g1 * 2048 + ch];
        const float* w   = &sW[e * 32];
        const float* in0 = &sIn[(2 * g0) * 16];
        #pragma unroll
        for (int j = 0; j < 32; j++) acc = fmaf(in0[j], w[j], acc);
        g_h[ob + ch] = acc;
        bf16 hv = __float2bfloat16_rn(acc);
        g_hhi[ob + ch] = hv;
        g_hlo[ob + ch] = __float2bfloat16_rn(acc - __bfloat162float(hv));
    }
}

// ---------------- mma.sync bf16x3 GEMM: C[M,N] = A[M,K] @ B[N,K]^T ----------
// CTA tile 128x128, K-chunk 32, 2-stage cp.async pipeline.
// smem per stage: Ah|Al|Bh|Bl, each 128 rows x 80B pitch (pitch-40 bf16).
// A/B may be dir-concatenated along K (ksplit / dirStride, in elements).
#define HALF_B  10240
#define STAGE_B 40960

__global__ void __launch_bounds__(256)
tgemm(const bf16* __restrict__ Ah, const bf16* __restrict__ Al, int lda,
      int aKsplit, size_t aDirStride,
      const bf16* __restrict__ Bh, const bf16* __restrict__ Bl, int ldb,
      int bKsplit, size_t bDirStride,
      float* __restrict__ C, int ldc, int K) {
    extern __shared__ char smem[];
    uint32_t sb = smem_u32(smem);
    int tid = threadIdx.x, lane = tid & 31, wid = tid >> 5;
    int bm = blockIdx.x * 128, bn = blockIdx.y * 128;
    int wm = (wid >> 2) * 64, wn = (wid & 3) * 32;

    float acc[4][4][4] = {};
    int NK = K / 32;

    auto load = [&](int buf, int chunk) {
        int k0 = chunk * 32;
        size_t aoff = (k0 < aKsplit) ? (size_t)k0 : aDirStride + (size_t)(k0 - aKsplit);
        size_t boff = (k0 < bKsplit) ? (size_t)k0 : bDirStride + (size_t)(k0 - bKsplit);
        uint32_t st = sb + buf * STAGE_B;
        #pragma unroll
        for (int i = 0; i < 2; i++) {
            int idx = tid * 2 + i;
            int row = idx >> 2, c = idx & 3;
            uint32_t d = st + row * 80 + c * 16;
            size_t ga = (size_t)(bm + row) * lda + aoff + c * 8;
            size_t gb = (size_t)(bn + row) * ldb + boff + c * 8;
            cpa16(d,              Ah + ga);
            cpa16(d + HALF_B,     Al + ga);
            cpa16(d + 2 * HALF_B, Bh + gb);
            cpa16(d + 3 * HALF_B, Bl + gb);
        }
        asm volatile("cp.async.commit_group;" ::: "memory");
    };

    load(0, 0);
    load(1, 1);

    for (int i = 0; i < NK; i++) {
        if (i == NK - 1) asm volatile("cp.async.wait_group 0;" ::: "memory");
        else             asm volatile("cp.async.wait_group 1;" ::: "memory");
        __syncthreads();
        uint32_t st = sb + (i & 1) * STAGE_B;
        #pragma unroll
        for (int s = 0; s < 2; s++) {
            int kb = s * 32;  // byte offset of k16 step
            uint32_t ah[4][4], al[4][4], bh[2][4], bl[2][4];
            int arow = wm + (lane & 7) + ((lane & 8) ? 8 : 0);
            int acol = ((lane & 16) ? 16 : 0) + kb;
            #pragma unroll
            for (int mt = 0; mt < 4; mt++) {
                uint32_t ad = st + (arow + mt * 16) * 80 + acol;
                ldsm4(ad, ah[mt]);
                ldsm4(ad + HALF_B, al[mt]);
            }
            int brow = wn + (lane & 7) + ((lane & 16) ? 8 : 0);
            int bcol = ((lane & 8) ? 16 : 0) + kb;
            #pragma unroll
            for (int bt = 0; bt < 2; bt++) {
                uint32_t bd = st + 2 * HALF_B + (brow + bt * 16) * 80 + bcol;
                ldsm4(bd, bh[bt]);
                ldsm4(bd + HALF_B, bl[bt]);
            }
            #pragma unroll
            for (int mt = 0; mt < 4; mt++)
                #pragma unroll
                for (int nt = 0; nt < 4; nt++) {
                    uint32_t h0 = bh[nt >> 1][(nt & 1) * 2];
                    uint32_t h1 = bh[nt >> 1][(nt & 1) * 2 + 1];
                    uint32_t l0 = bl[nt >> 1][(nt & 1) * 2];
                    uint32_t l1 = bl[nt >> 1][(nt & 1) * 2 + 1];
                    mma_bf16(acc[mt][nt], ah[mt], h0, h1);
                    mma_bf16(acc[mt][nt], ah[mt], l0, l1);
                    mma_bf16(acc[mt][nt], al[mt], h0, h1);
                }
        }
        __syncthreads();
        if (i + 2 < NK) load(i & 1, i + 2);
    }

    #pragma unroll
    for (int mt = 0; mt < 4; mt++) {
        int r0 = bm + wm + mt * 16 + (lane >> 2);
        #pragma unroll
        for (int nt = 0; nt < 4; nt++) {
            int col = bn + wn + nt * 8 + (lane & 3) * 2;
            float2 v0 = make_float2(acc[mt][nt][0], acc[mt][nt][1]);
            float2 v1 = make_float2(acc[mt][nt][2], acc[mt][nt][3]);
            *(float2*)&C[(size_t)r0 * ldc + col] = v0;
            *(float2*)&C[(size_t)(r0 + 8) * ldc + col] = v1;
        }
    }
}

// ---------------- SIMT SGEMM (small GEMMs): C = A @ B^T --------------------
template <int EPI>
__global__ void __launch_bounds__(256)
sgemm(const float* __restrict__ A, int lda,
      const float* __restrict__ B, int ldb,
      float* __restrict__ C, int ldc,
      int M, int N, int K, const float* __restrict__ bias) {
    __shared__ float As[8][128];
    __shared__ float Bs[8][128];
    int tid = threadIdx.x;
    int bm = blockIdx.y * 128, bn = blockIdx.x * 128;
    int lr = tid >> 1, lk = (tid & 1) * 4;
    int ty = tid >> 4, tx = tid & 15;
    float acc[8][8] = {};
    const float* Ap = A + (size_t)(bm + lr) * lda + lk;
    const float* Bp = B + (size_t)(bn + lr) * ldb + lk;
    bool bvalid = (bn + lr) < N;
    for (int k0 = 0; k0 < K; k0 += 8) {
        float4 av = *(const float4*)(Ap + k0);
        float4 bv = bvalid ? *(const float4*)(Bp + k0) : make_float4(0.f, 0.f, 0.f, 0.f);
        __syncthreads();
        As[lk + 0][lr] = av.x; As[lk + 1][lr] = av.y;
        As[lk + 2][lr] = av.z; As[lk + 3][lr] = av.w;
        Bs[lk + 0][lr] = bv.x; Bs[lk + 1][lr] = bv.y;
        Bs[lk + 2][lr] = bv.z; Bs[lk + 3][lr] = bv.w;
        __syncthreads();
        #pragma unroll
        for (int k = 0; k < 8; k++) {
            float a[8], bb[8];
            *(float4*)&a[0]  = *(const float4*)&As[k][ty * 8];
            *(float4*)&a[4]  = *(const float4*)&As[k][ty * 8 + 4];
            *(float4*)&bb[0] = *(const float4*)&Bs[k][tx * 8];
            *(float4*)&bb[4] = *(const float4*)&Bs[k][tx * 8 + 4];
            #pragma unroll
            for (int i = 0; i < 8; i++)
                #pragma unroll
                for (int j = 0; j < 8; j++)
                    acc[i][j] = fmaf(a[i], bb[j], acc[i][j]);
        }
    }
    #pragma unroll
    for (int i = 0; i < 8; i++) {
        int row = bm + ty * 8 + i;
        float* Cr = C + (size_t)row * ldc + bn + tx * 8;
        #pragma unroll
        for (int j = 0; j < 8; j++) {
            int col = bn + tx * 8 + j;
            if (col < N) {
                float v = acc[i][j];
                if (EPI == 1) {
                    v += bias[col];
                    v = (v > 20.f) ? v : log1pf(expf(v));
                }
                Cr[j] = v;
            }
        }
    }
}

// ---------------- 2) depthwise conv + silu ---------------------------------
__global__ void conv_silu_kernel(const float* __restrict__ cw,
                                 const float* __restrict__ cb) {
    int d = blockIdx.x * 256 + threadIdx.x;
    int b = blockIdx.y, dir = blockIdx.z;
    float w0 = cw[(dir * DIN + d) * 4 + 0];
    float w1 = cw[(dir * DIN + d) * 4 + 1];
    float w2 = cw[(dir * DIN + d) * 4 + 2];
    float w3 = cw[(dir * DIN + d) * 4 + 3];
    float bias = cb[dir * DIN + d];
    const float* src = g_xz + (size_t)(b * LSEQ) * XZW + dir * 8192 + d;
    float* dst = g_u[dir] + (size_t)(b * LSEQ) * DIN + d;
    float x1 = 0.f, x2 = 0.f, x3 = 0.f;
    if (dir == 0) {
        for (int l = 0; l < LSEQ; l++) {
            float x0 = src[(size_t)l * XZW];
            float v = bias + w0 * x3 + w1 * x2 + w2 * x1 + w3 * x0;
            dst[(size_t)l * DIN] = siluf(v);
            x3 = x2; x2 = x1; x1 = x0;
        }
    } else {
        for (int l = LSEQ - 1; l >= 0; l--) {
            float x0 = src[(size_t)l * XZW];
            float v = bias + w3 * x0 + w2 * x1 + w1 * x2 + w0 * x3;
            dst[(size_t)l * DIN] = siluf(v);
            x3 = x2; x2 = x1; x1 = x0;
        }
    }
}

// ---------------- 3) selective scan + gating (emits y hi/lo bf16) -----------
__global__ void scan_kernel(const float* __restrict__ A_log,
                            const float* __restrict__ Dp) {
    int d = blockIdx.x * 256 + threadIdx.x;
    int b = blockIdx.y, dir = blockIdx.z;
    __shared__ float sBC[32];
    float Aa[16];
    #pragma unroll
    for (int s = 0; s < 16; s++)
        Aa[s] = -expf(A_log[(size_t)(dir * DIN + d) * 16 + s]);
    float dpv = Dp[dir * DIN + d];
    const float* dtp = g_dt[dir] + d;
    const float* up  = g_u[dir] + d;
    const float* xdp = g_xdbl[dir];
    const float* zp  = g_xz + (size_t)dir * 8192 + 4096 + d;
    bf16* yh = g_yhi[dir] + d;
    bf16* yl = g_ylo[dir] + d;
    float st[16];
    #pragma unroll
    for (int s = 0; s < 16; s++) st[s] = 0.f;
    for (int step = 0; step < LSEQ; step++) {
        int l = dir ? (LSEQ - 1 - step) : step;
        size_t t = (size_t)b * LSEQ + l;
        __syncthreads();
        if (threadIdx.x < 32) sBC[threadIdx.x] = xdp[t * 160 + 128 + threadIdx.x];
        __syncthreads();
        float dtv = dtp[t * DIN];
        float uv  = up[t * DIN];
        float zv  = zp[t * XZW];
        float du  = dtv * uv;
        float accv = 0.f;
        #pragma unroll
        for (int s = 0; s < 16; s++) {
            float dA = __expf(dtv * Aa[s]);
            st[s] = fmaf(st[s], dA, du * sBC[s]);
            accv = fmaf(st[s], sBC[16 + s], accv);
        }
        float yv = (accv + uv * dpv) * siluf(zv);
        bf16 hv = __float2bfloat16_rn(yv);
        yh[t * DIN] = hv;
        yl[t * DIN] = __float2bfloat16_rn(yv - __bfloat162float(hv));
    }
}

// ---------------- 4) residual add + LayerNorm ------------------------------
__global__ void addln_kernel(const float* __restrict__ g,
                             const float* __restrict__ be) {
    int t = blockIdx.x, tid = threadIdx.x;
    size_t base = (size_t)t * DM;
    float v[8], s = 0.f, s2 = 0.f;
    #pragma unroll
    for (int i = 0; i < 8; i++) {
        int idx = tid + i * 256;
        float val = g_h[base + idx] + g_o[base + idx];
        v[i] = val; s += val; s2 += val * val;
    }
    __shared__ float rs[8], rs2[8];
    #pragma unroll
    for (int off = 16; off; off >>= 1) {
        s  += __shfl_xor_sync(0xffffffffu, s,  off);
        s2 += __shfl_xor_sync(0xffffffffu, s2, off);
    }
    if ((tid & 31) == 0) { rs[tid >> 5] = s; rs2[tid >> 5] = s2; }
    __syncthreads();
    float S = 0.f, S2 = 0.f;
    #pragma unroll
    for (int i = 0; i < 8; i++) { S += rs[i]; S2 += rs2[i]; }
    float mean = S * (1.f / 2048.f);
    float var  = S2 * (1.f / 2048.f) - mean * mean;
    float rinv = rsqrtf(var + 1e-5f);
    #pragma unroll
    for (int i = 0; i < 8; i++) {
        int idx = tid + i * 256;
        g_h2[base + idx] = (v[i] - mean) * rinv * g[idx] + be[idx];
    }
}

// ---------------- 5) 31x31 SAME conv over (256 x 2048) ---------------------
__global__ void decconv_kernel(const float* __restrict__ kw) {
    __shared__ float sIn[62 * 62];
    __shared__ float sW[961];
    int w0 = blockIdx.x * 32, h0 = blockIdx.y * 32, b = blockIdx.z;
    int tid = threadIdx.x;
    for (int i = tid; i < 62 * 62; i += 256) {
        int r = i / 62, c = i % 62;
        int gh = h0 - 15 + r, gw = w0 - 15 + c;
        float v = 0.f;
        if (gh >= 0 && gh < 256 && gw >= 0 && gw < 2048)
            v = g_h2[(size_t)(b * 256 + gh) * 2048 + gw];
        sIn[i] = v;
    }
    for (int i = tid; i < 961; i += 256) sW[i] = kw[i];
    __syncthreads();
    int tx = tid & 31, tyb = tid >> 5;
    float acc[4] = {0.f, 0.f, 0.f, 0.f};
    for (int ky = 0; ky < 31; ky++) {
        #pragma unroll
        for (int kx = 0; kx < 31; kx++) {
            float w = sW[ky * 31 + kx];
            #pragma unroll
            for (int i = 0; i < 4; i++)
                acc[i] = fmaf(sIn[(tyb + 8 * i + ky) * 62 + tx + kx], w, acc[i]);
        }
    }
    #pragma unroll
    for (int i = 0; i < 4; i++) {
        int hh = h0 + tyb + 8 * i;
        g_d[(size_t)(b * 256 + hh) * 2048 + w0 + tx] = acc[i];
    }
}

// ---------------- 6) convT reconstruction ----------------------------------
__global__ void rec_kernel(const float* __restrict__ wt,
                           const float* __restrict__ wb,
                           float* __restrict__ out) {
    __shared__ float sW[2048];
    for (int i = threadIdx.x; i < 2048; i += 256) sW[i] = wt[i];
    __syncthreads();
    int idx = blockIdx.x * 256 + threadIdx.x;
    int ww = idx & 4095;
    int hh = (idx >> 12) & 63;
    int b  = idx >> 18;
    int g0 = hh >> 1, ii = hh & 1, g1 = ww >> 4, jj = ww & 15;
    const float* dp = g_d + (size_t)(b * 256 + g1) * 2048 + g0;
    float acc = wb[0];
    #pragma unroll 8
    for (int c = 0; c < 64; c++)
        acc = fmaf(dp[c * 32], sW[c * 32 + ii * 16 + jj], acc);
    out[idx] = acc;
}

// ---------------------------------------------------------------------------
extern "C" void kernel_launch(void* const* d_in, const int* in_sizes, int n_in,
                              void* d_out, int out_size) {
    const float* x          = (const float*)d_in[0];
    const void*  mk         = d_in[1];
    const float* proj_w     = (const float*)d_in[2];
    const float* proj_b     = (const float*)d_in[3];
    const float* pos_embed  = (const float*)d_in[4];
    const float* in_proj_w  = (const float*)d_in[5];
    const float* conv_w     = (const float*)d_in[6];
    const float* conv_b     = (const float*)d_in[7];
    const float* x_proj_w   = (const float*)d_in[8];
    const float* dt_proj_w  = (const float*)d_in[9];
    const float* dt_proj_b  = (const float*)d_in[10];
    const float* A_log      = (const float*)d_in[11];
    const float* Dp         = (const float*)d_in[12];
    const float* out_proj_w = (const float*)d_in[13];
    const float* ln_g       = (const float*)d_in[14];
    const float* ln_b       = (const float*)d_in[15];
    const float* dec_conv_w = (const float*)d_in[16];
    const float* convT_w    = (const float*)d_in[17];
    const float* convT_b    = (const float*)d_in[18];
    float* out = (float*)d_out;

    float *p_xz, *p_u, *p_xdbl, *p_dt, *p_o;
    bf16 *p_hhi, *p_hlo, *p_yhi, *p_ylo, *p_inwhi, *p_inwlo, *p_outwhi, *p_outwlo;
    cudaGetSymbolAddress((void**)&p_hhi,    g_hhi);
    cudaGetSymbolAddress((void**)&p_hlo,    g_hlo);
    cudaGetSymbolAddress((void**)&p_xz,     g_xz);
    cudaGetSymbolAddress((void**)&p_u,      g_u);
    cudaGetSymbolAddress((void**)&p_xdbl,   g_xdbl);
    cudaGetSymbolAddress((void**)&p_dt,     g_dt);
    cudaGetSymbolAddress((void**)&p_yhi,    g_yhi);
    cudaGetSymbolAddress((void**)&p_ylo,    g_ylo);
    cudaGetSymbolAddress((void**)&p_o,      g_o);
    cudaGetSymbolAddress((void**)&p_inwhi,  g_inwhi);
    cudaGetSymbolAddress((void**)&p_inwlo,  g_inwlo);
    cudaGetSymbolAddress((void**)&p_outwhi, g_outwhi);
    cudaGetSymbolAddress((void**)&p_outwlo, g_outwlo);

    cudaFuncSetAttribute(tgemm, cudaFuncAttributeMaxDynamicSharedMemorySize,
                         2 * STAGE_B);
    const int TG_SMEM = 2 * STAGE_B;
    const int BIGK = 1 << 30;

    // 0) mask normalize + weight splits
    mask_detect_kernel<<<1, 256>>>((const unsigned char*)mk);
    mask_norm_kernel<<<NMASK / 256, 256>>>(mk);
    split_kernel<<<4096, 256>>>(in_proj_w, p_inwhi, p_inwlo, XZW * DM);
    split_kernel<<<4096, 256>>>(out_proj_w, p_outwhi, p_outwlo, 2 * DM * DIN);

    // 1) patch embed + pos embed -> g_h (+hi/lo)
    patch_kernel<<<dim3(256, 8), 256>>>(x, proj_w, proj_b, pos_embed);

    // 2) in_proj (both dirs fused): [2048,2048] @ [16384,2048]^T -> g_xz
    tgemm<<<dim3(TOKS / 128, XZW / 128), 256, TG_SMEM>>>(
        p_hhi, p_hlo, DM, BIGK, 0,
        p_inwhi, p_inwlo, DM, BIGK, 0,
        p_xz, XZW, DM);

    // 3) depthwise conv + silu
    conv_silu_kernel<<<dim3(16, 8, 2), 256>>>(conv_w, conv_b);

    // 4) x_proj and dt_proj per direction (SIMT)
    for (int dir = 0; dir < 2; dir++) {
        sgemm<0><<<dim3(2, TOKS / 128), 256>>>(
            p_u + (size_t)dir * TOKS * DIN, DIN,
            x_proj_w + (size_t)dir * 160 * DIN, DIN,
            p_xdbl + (size_t)dir * TOKS * 160, 160,
            TOKS, 160, DIN, nullptr);
        sgemm<1><<<dim3(DIN / 128, TOKS / 128), 256>>>(
            p_xdbl + (size_t)dir * TOKS * 160, 160,
            dt_proj_w + (size_t)dir * DIN * DTR, DTR,
            p_dt + (size_t)dir * TOKS * DIN, DIN,
            TOKS, DIN, DTR, dt_proj_b + dir * DIN);
    }

    // 5) selective scan + gating -> y hi/lo (bf16)
    scan_kernel<<<dim3(16, 8, 2), 256>>>(A_log, Dp);

    // 6) out_proj, both dirs fused along K=8192: o = [y0|y1] @ [W0|W1]^T
    tgemm<<<dim3(TOKS / 128, DM / 128), 256, TG_SMEM>>>(
        p_yhi, p_ylo, DIN, DIN, (size_t)TOKS * DIN,
        p_outwhi, p_outwlo, DIN, DIN, (size_t)DM * DIN,
        p_o, DM, 2 * DIN);

    // 7) residual + LayerNorm
    addln_kernel<<<TOKS, 256>>>(ln_g, ln_b);

    // 8) 31x31 decoder conv
    decconv_kernel<<<dim3(64, 8, 8), 256>>>(dec_conv_w);

    // 9) convT reconstruction
    rec_kernel<<<8192, 256>>>(convT_w, convT_b, out);

    // 10) pass-through x
    if (out_size >= 2 * 2097152) {
        cudaMemcpyAsync(out + 2097152, x, (size_t)2097152 * sizeof(float),
                        cudaMemcpyDeviceToDevice, 0);
    }
}

// round 6
// speedup vs baseline: 1.9989x; 1.1950x over previous
#include <cuda_runtime.h>
#include <cuda_bf16.h>
#include <math.h>
#include <stdint.h>

// ---------------------------------------------------------------------------
// FEMBA forward. All GEMMs (in_proj, x_proj, dt_proj, out_proj) on mma.sync
// bf16 with 2-way split (3 products) for fp32-level accuracy.
// ---------------------------------------------------------------------------

#define TOKS 2048
#define LSEQ 256
#define DM   2048
#define DIN  4096
#define DS   16
#define DTR  128
#define XZW  16384
#define XDP  256      // padded xdbl pitch (160 -> 256)
#define NMASK (8 * 64 * 4096)

typedef __nv_bfloat16 bf16;

// ---------------- scratch (device globals) ----------------------------------
__device__ float g_h   [TOKS * DM];
__device__ bf16  g_hhi [TOKS * DM];
__device__ bf16  g_hlo [TOKS * DM];
__device__ float g_h2  [TOKS * DM];
__device__ float g_xz  [(size_t)TOKS * XZW];
__device__ float g_u   [2][TOKS * DIN];
__device__ bf16  g_uhi [2][TOKS * DIN];
__device__ bf16  g_ulo [2][TOKS * DIN];
__device__ float g_xdbl[2][TOKS * XDP];
__device__ bf16  g_xdhi[2][TOKS * DTR];
__device__ bf16  g_xdlo[2][TOKS * DTR];
__device__ float g_dt  [2][TOKS * DIN];
__device__ bf16  g_yhi [2][TOKS * DIN];
__device__ bf16  g_ylo [2][TOKS * DIN];
__device__ float g_o   [TOKS * DM];
__device__ float g_d   [TOKS * DM];
__device__ bf16  g_inwhi[(size_t)XZW * DM];
__device__ bf16  g_inwlo[(size_t)XZW * DM];
__device__ bf16  g_outwhi[(size_t)2 * DM * DIN];
__device__ bf16  g_outwlo[(size_t)2 * DM * DIN];
__device__ bf16  g_xwhi[(size_t)2 * 256 * DIN];   // x_proj_w padded 160->256
__device__ bf16  g_xwlo[(size_t)2 * 256 * DIN];
__device__ bf16  g_dtwhi[(size_t)2 * DIN * DTR];
__device__ bf16  g_dtwlo[(size_t)2 * DIN * DTR];
__device__ unsigned char g_mask[NMASK];
__device__ int g_mask_mode;

__device__ __forceinline__ float siluf(float x) { return x / (1.f + __expf(-x)); }

__device__ __forceinline__ uint32_t smem_u32(const void* p) {
    uint32_t a;
    asm("{ .reg .u64 t; cvta.to.shared.u64 t, %1; cvt.u32.u64 %0, t; }" : "=r"(a) : "l"(p));
    return a;
}
__device__ __forceinline__ void cpa16(uint32_t dst, const void* src) {
    asm volatile("cp.async.cg.shared.global [%0], [%1], 16;" :: "r"(dst), "l"(src));
}
__device__ __forceinline__ void ldsm4(uint32_t addr, uint32_t* r) {
    asm volatile("ldmatrix.sync.aligned.m8n8.x4.shared.b16 {%0,%1,%2,%3}, [%4];"
                 : "=r"(r[0]), "=r"(r[1]), "=r"(r[2]), "=r"(r[3]) : "r"(addr));
}
__device__ __forceinline__ void mma_bf16(float* c, const uint32_t* a,
                                         uint32_t b0, uint32_t b1) {
    asm volatile("mma.sync.aligned.m16n8k16.row.col.f32.bf16.bf16.f32 "
                 "{%0,%1,%2,%3}, {%4,%5,%6,%7}, {%8,%9}, {%0,%1,%2,%3};"
                 : "+f"(c[0]), "+f"(c[1]), "+f"(c[2]), "+f"(c[3])
                 : "r"(a[0]), "r"(a[1]), "r"(a[2]), "r"(a[3]), "r"(b0), "r"(b1));
}

// ---------------- 0) mask dtype sniff + normalize ---------------------------
__global__ void mask_detect_kernel(const unsigned char* __restrict__ m) {
    __shared__ int cnt;
    if (threadIdx.x == 0) cnt = 0;
    __syncthreads();
    int local = 0;
    for (int i = threadIdx.x * 4 + 1; i < 65536; i += 1024)
        if (m[i]) local++;
    atomicAdd(&cnt, local);
    __syncthreads();
    if (threadIdx.x == 0) g_mask_mode = (cnt > 0) ? 0 : 1;
}
__global__ void mask_norm_kernel(const void* __restrict__ m) {
    int i = blockIdx.x * 256 + threadIdx.x;
    if (i >= NMASK) return;
    if (g_mask_mode == 0) g_mask[i] = ((const unsigned char*)m)[i] ? 1 : 0;
    else                  g_mask[i] = (((const unsigned int*)m)[i] != 0u) ? 1 : 0;
}

// ---------------- splits -----------------------------------------------------
__global__ void split_kernel(const float* __restrict__ src, bf16* __restrict__ hi,
                             bf16* __restrict__ lo, int n) {
    for (int i = blockIdx.x * 256 + threadIdx.x; i < n; i += gridDim.x * 256) {
        float a = src[i];
        bf16 h = __float2bfloat16_rn(a);
        hi[i] = h;
        lo[i] = __float2bfloat16_rn(a - __bfloat162float(h));
    }
}
// x_proj_w [2,160,4096] -> padded [2,256,4096] hi/lo (rows >=160 zero)
__global__ void padsplit_xw_kernel(const float* __restrict__ src) {
    int i = blockIdx.x * 256 + threadIdx.x;   // over 2*256*4096
    int c = i & 4095;
    int r = (i >> 12) & 255;
    int dir = i >> 20;
    float a = (r < 160) ? src[(size_t)(dir * 160 + r) * 4096 + c] : 0.f;
    bf16 h = __float2bfloat16_rn(a);
    g_xwhi[i] = h;
    g_xwlo[i] = __float2bfloat16_rn(a - __bfloat162float(h));
}
// xdbl[:, :128] (pitch 256) -> packed hi/lo [TOKS,128] per dir
__global__ void split_xd_kernel() {
    int i = blockIdx.x * 256 + threadIdx.x;   // over 2*2048*128
    int c = i & 127;
    int t = (i >> 7) & 2047;
    int dir = i >> 18;
    float a = g_xdbl[dir][t * XDP + c];
    bf16 h = __float2bfloat16_rn(a);
    g_xdhi[dir][t * DTR + c] = h;
    g_xdlo[dir][t * DTR + c] = __float2bfloat16_rn(a - __bfloat162float(h));
}

// ---------------- 1) patch embed + pos embed --------------------------------
__global__ void patch_kernel(const float* __restrict__ x,
                             const float* __restrict__ pw,
                             const float* __restrict__ pb,
                             const float* __restrict__ pos) {
    int g1 = blockIdx.x, b = blockIdx.y, tid = threadIdx.x;
    __shared__ float sIn[64 * 16];
    __shared__ float sW [64 * 32];
    for (int i = tid; i < 1024; i += 256) {
        int r = i >> 4, c = i & 15;
        size_t gi = (size_t)b * 64 * 4096 + (size_t)r * 4096 + g1 * 16 + c;
        float v = x[gi];
        if (g_mask[gi]) v = 0.f;
        sIn[i] = v;
    }
    for (int i = tid; i < 2048; i += 256) sW[i] = pw[i];
    __syncthreads();
    size_t ob = (size_t)(b * 256 + g1) * 2048;
    #pragma unroll
    for (int rep = 0; rep < 8; rep++) {
        int ch = tid + rep * 256;
        int e = ch >> 5, g0 = ch & 31;
        float acc = pb[e] + pos[g1 * 2048 + ch];
        const float* w   = &sW[e * 32];
        const float* in0 = &sIn[(2 * g0) * 16];
        #pragma unroll
        for (int j = 0; j < 32; j++) acc = fmaf(in0[j], w[j], acc);
        g_h[ob + ch] = acc;
        bf16 hv = __float2bfloat16_rn(acc);
        g_hhi[ob + ch] = hv;
        g_hlo[ob + ch] = __float2bfloat16_rn(acc - __bfloat162float(hv));
    }
}

// ---------------- mma.sync bf16x3 GEMM: C[M,N] = A[M,K] @ B[N,K]^T ----------
// CTA tile 128x128, K-chunk 32, 3-stage cp.async ring, 1 barrier per chunk.
// EPI: 0 = store, 1 = softplus(acc + bias[col]).
#define HALF_B  10240
#define STAGE_B 40960
#define NSTG    3

template <int EPI>
__global__ void __launch_bounds__(256)
tgemm(const bf16* __restrict__ Ah, const bf16* __restrict__ Al, int lda,
      int aKsplit, size_t aDirStride,
      const bf16* __restrict__ Bh, const bf16* __restrict__ Bl, int ldb,
      int bKsplit, size_t bDirStride,
      float* __restrict__ C, int ldc, int K, const float* __restrict__ bias) {
    extern __shared__ char smem[];
    uint32_t sb = smem_u32(smem);
    int tid = threadIdx.x, lane = tid & 31, wid = tid >> 5;
    int bm = blockIdx.x * 128, bn = blockIdx.y * 128;
    int wm = (wid >> 2) * 64, wn = (wid & 3) * 32;

    float acc[4][4][4] = {};
    int NK = K / 32;

    auto load = [&](int chunk) {
        int k0 = chunk * 32;
        size_t aoff = (k0 < aKsplit) ? (size_t)k0 : aDirStride + (size_t)(k0 - aKsplit);
        size_t boff = (k0 < bKsplit) ? (size_t)k0 : bDirStride + (size_t)(k0 - bKsplit);
        uint32_t st = sb + (chunk % NSTG) * STAGE_B;
        #pragma unroll
        for (int i = 0; i < 2; i++) {
            int idx = tid * 2 + i;
            int row = idx >> 2, c = idx & 3;
            uint32_t d = st + row * 80 + c * 16;
            size_t ga = (size_t)(bm + row) * lda + aoff + c * 8;
            size_t gb = (size_t)(bn + row) * ldb + boff + c * 8;
            cpa16(d,              Ah + ga);
            cpa16(d + HALF_B,     Al + ga);
            cpa16(d + 2 * HALF_B, Bh + gb);
            cpa16(d + 3 * HALF_B, Bl + gb);
        }
        asm volatile("cp.async.commit_group;" ::: "memory");
    };

    load(0);
    if (NK > 1) load(1);

    for (int i = 0; i < NK; i++) {
        if (i + 1 < NK) asm volatile("cp.async.wait_group 1;" ::: "memory");
        else            asm volatile("cp.async.wait_group 0;" ::: "memory");
        __syncthreads();
        if (i + 2 < NK) load(i + 2);   // ring slot (i+2)%3 == (i-1)%3: freed
        uint32_t st = sb + (i % NSTG) * STAGE_B;
        #pragma unroll
        for (int s = 0; s < 2; s++) {
            int kb = s * 32;
            uint32_t ah[4][4], al[4][4], bh[2][4], bl[2][4];
            int arow = wm + (lane & 7) + ((lane & 8) ? 8 : 0);
            int acol = ((lane & 16) ? 16 : 0) + kb;
            #pragma unroll
            for (int mt = 0; mt < 4; mt++) {
                uint32_t ad = st + (arow + mt * 16) * 80 + acol;
                ldsm4(ad, ah[mt]);
                ldsm4(ad + HALF_B, al[mt]);
            }
            int brow = wn + (lane & 7) + ((lane & 16) ? 8 : 0);
            int bcol = ((lane & 8) ? 16 : 0) + kb;
            #pragma unroll
            for (int bt = 0; bt < 2; bt++) {
                uint32_t bd = st + 2 * HALF_B + (brow + bt * 16) * 80 + bcol;
                ldsm4(bd, bh[bt]);
                ldsm4(bd + HALF_B, bl[bt]);
            }
            #pragma unroll
            for (int mt = 0; mt < 4; mt++)
                #pragma unroll
                for (int nt = 0; nt < 4; nt++) {
                    uint32_t h0 = bh[nt >> 1][(nt & 1) * 2];
                    uint32_t h1 = bh[nt >> 1][(nt & 1) * 2 + 1];
                    uint32_t l0 = bl[nt >> 1][(nt & 1) * 2];
                    uint32_t l1 = bl[nt >> 1][(nt & 1) * 2 + 1];
                    mma_bf16(acc[mt][nt], ah[mt], h0, h1);
                    mma_bf16(acc[mt][nt], ah[mt], l0, l1);
                    mma_bf16(acc[mt][nt], al[mt], h0, h1);
                }
        }
        __syncthreads();
    }

    #pragma unroll
    for (int mt = 0; mt < 4; mt++) {
        int r0 = bm + wm + mt * 16 + (lane >> 2);
        #pragma unroll
        for (int nt = 0; nt < 4; nt++) {
            int col = bn + wn + nt * 8 + (lane & 3) * 2;
            float v0 = acc[mt][nt][0], v1 = acc[mt][nt][1];
            float v2 = acc[mt][nt][2], v3 = acc[mt][nt][3];
            if (EPI == 1) {
                float b0 = bias[col], b1 = bias[col + 1];
                v0 += b0; v1 += b1; v2 += b0; v3 += b1;
                v0 = (v0 > 20.f) ? v0 : log1pf(expf(v0));
                v1 = (v1 > 20.f) ? v1 : log1pf(expf(v1));
                v2 = (v2 > 20.f) ? v2 : log1pf(expf(v2));
                v3 = (v3 > 20.f) ? v3 : log1pf(expf(v3));
            }
            *(float2*)&C[(size_t)r0 * ldc + col] = make_float2(v0, v1);
            *(float2*)&C[(size_t)(r0 + 8) * ldc + col] = make_float2(v2, v3);
        }
    }
}

// ---------------- 2) depthwise conv + silu (emits u fp32 + hi/lo) -----------
__global__ void conv_silu_kernel(const float* __restrict__ cw,
                                 const float* __restrict__ cb) {
    int d = blockIdx.x * 256 + threadIdx.x;
    int b = blockIdx.y, dir = blockIdx.z;
    float w0 = cw[(dir * DIN + d) * 4 + 0];
    float w1 = cw[(dir * DIN + d) * 4 + 1];
    float w2 = cw[(dir * DIN + d) * 4 + 2];
    float w3 = cw[(dir * DIN + d) * 4 + 3];
    float bias = cb[dir * DIN + d];
    const float* src = g_xz + (size_t)(b * LSEQ) * XZW + dir * 8192 + d;
    float* dst = g_u[dir] + (size_t)(b * LSEQ) * DIN + d;
    bf16* dh = g_uhi[dir] + (size_t)(b * LSEQ) * DIN + d;
    bf16* dl = g_ulo[dir] + (size_t)(b * LSEQ) * DIN + d;
    float x1 = 0.f, x2 = 0.f, x3 = 0.f;
    if (dir == 0) {
        for (int l = 0; l < LSEQ; l++) {
            float x0 = src[(size_t)l * XZW];
            float v = siluf(bias + w0 * x3 + w1 * x2 + w2 * x1 + w3 * x0);
            dst[(size_t)l * DIN] = v;
            bf16 hv = __float2bfloat16_rn(v);
            dh[(size_t)l * DIN] = hv;
            dl[(size_t)l * DIN] = __float2bfloat16_rn(v - __bfloat162float(hv));
            x3 = x2; x2 = x1; x1 = x0;
        }
    } else {
        for (int l = LSEQ - 1; l >= 0; l--) {
            float x0 = src[(size_t)l * XZW];
            float v = siluf(bias + w3 * x0 + w2 * x1 + w1 * x2 + w0 * x3);
            dst[(size_t)l * DIN] = v;
            bf16 hv = __float2bfloat16_rn(v);
            dh[(size_t)l * DIN] = hv;
            dl[(size_t)l * DIN] = __float2bfloat16_rn(v - __bfloat162float(hv));
            x3 = x2; x2 = x1; x1 = x0;
        }
    }
}

// ---------------- 3) selective scan + gating (emits y hi/lo bf16) -----------
__global__ void scan_kernel(const float* __restrict__ A_log,
                            const float* __restrict__ Dp) {
    int d = blockIdx.x * 256 + threadIdx.x;
    int b = blockIdx.y, dir = blockIdx.z;
    __shared__ float sBC[32];
    float Aa[16];
    #pragma unroll
    for (int s = 0; s < 16; s++)
        Aa[s] = -expf(A_log[(size_t)(dir * DIN + d) * 16 + s]);
    float dpv = Dp[dir * DIN + d];
    const float* dtp = g_dt[dir] + d;
    const float* up  = g_u[dir] + d;
    const float* xdp = g_xdbl[dir];
    const float* zp  = g_xz + (size_t)dir * 8192 + 4096 + d;
    bf16* yh = g_yhi[dir] + d;
    bf16* yl = g_ylo[dir] + d;
    float st[16];
    #pragma unroll
    for (int s = 0; s < 16; s++) st[s] = 0.f;
    for (int step = 0; step < LSEQ; step++) {
        int l = dir ? (LSEQ - 1 - step) : step;
        size_t t = (size_t)b * LSEQ + l;
        __syncthreads();
        if (threadIdx.x < 32) sBC[threadIdx.x] = xdp[t * XDP + 128 + threadIdx.x];
        __syncthreads();
        float dtv = dtp[t * DIN];
        float uv  = up[t * DIN];
        float zv  = zp[t * XZW];
        float du  = dtv * uv;
        float accv = 0.f;
        #pragma unroll
        for (int s = 0; s < 16; s++) {
            float dA = __expf(dtv * Aa[s]);
            st[s] = fmaf(st[s], dA, du * sBC[s]);
            accv = fmaf(st[s], sBC[16 + s], accv);
        }
        float yv = (accv + uv * dpv) * siluf(zv);
        bf16 hv = __float2bfloat16_rn(yv);
        yh[t * DIN] = hv;
        yl[t * DIN] = __float2bfloat16_rn(yv - __bfloat162float(hv));
    }
}

// ---------------- 4) residual add + LayerNorm -------------------------------
__global__ void addln_kernel(const float* __restrict__ g,
                             const float* __restrict__ be) {
    int t = blockIdx.x, tid = threadIdx.x;
    size_t base = (size_t)t * DM;
    float v[8], s = 0.f, s2 = 0.f;
    #pragma unroll
    for (int i = 0; i < 8; i++) {
        int idx = tid + i * 256;
        float val = g_h[base + idx] + g_o[base + idx];
        v[i] = val; s += val; s2 += val * val;
    }
    __shared__ float rs[8], rs2[8];
    #pragma unroll
    for (int off = 16; off; off >>= 1) {
        s  += __shfl_xor_sync(0xffffffffu, s,  off);
        s2 += __shfl_xor_sync(0xffffffffu, s2, off);
    }
    if ((tid & 31) == 0) { rs[tid >> 5] = s; rs2[tid >> 5] = s2; }
    __syncthreads();
    float S = 0.f, S2 = 0.f;
    #pragma unroll
    for (int i = 0; i < 8; i++) { S += rs[i]; S2 += rs2[i]; }
    float mean = S * (1.f / 2048.f);
    float var  = S2 * (1.f / 2048.f) - mean * mean;
    float rinv = rsqrtf(var + 1e-5f);
    #pragma unroll
    for (int i = 0; i < 8; i++) {
        int idx = tid + i * 256;
        g_h2[base + idx] = (v[i] - mean) * rinv * g[idx] + be[idx];
    }
}

// ---------------- 5) 31x31 SAME conv over (256 x 2048) ----------------------
__global__ void decconv_kernel(const float* __restrict__ kw) {
    __shared__ float sIn[62 * 62];
    __shared__ float sW[961];
    int w0 = blockIdx.x * 32, h0 = blockIdx.y * 32, b = blockIdx.z;
    int tid = threadIdx.x;
    for (int i = tid; i < 62 * 62; i += 256) {
        int r = i / 62, c = i % 62;
        int gh = h0 - 15 + r, gw = w0 - 15 + c;
        float v = 0.f;
        if (gh >= 0 && gh < 256 && gw >= 0 && gw < 2048)
            v = g_h2[(size_t)(b * 256 + gh) * 2048 + gw];
        sIn[i] = v;
    }
    for (int i = tid; i < 961; i += 256) sW[i] = kw[i];
    __syncthreads();
    int tx = tid & 31, tyb = tid >> 5;
    float acc[4] = {0.f, 0.f, 0.f, 0.f};
    for (int ky = 0; ky < 31; ky++) {
        #pragma unroll
        for (int kx = 0; kx < 31; kx++) {
            float w = sW[ky * 31 + kx];
            #pragma unroll
            for (int i = 0; i < 4; i++)
                acc[i] = fmaf(sIn[(tyb + 8 * i + ky) * 62 + tx + kx], w, acc[i]);
        }
    }
    #pragma unroll
    for (int i = 0; i < 4; i++) {
        int hh = h0 + tyb + 8 * i;
        g_d[(size_t)(b * 256 + hh) * 2048 + w0 + tx] = acc[i];
    }
}

// ---------------- 6) convT reconstruction -----------------------------------
__global__ void rec_kernel(const float* __restrict__ wt,
                           const float* __restrict__ wb,
                           float* __restrict__ out) {
    __shared__ float sW[2048];
    for (int i = threadIdx.x; i < 2048; i += 256) sW[i] = wt[i];
    __syncthreads();
    int idx = blockIdx.x * 256 + threadIdx.x;
    int ww = idx & 4095;
    int hh = (idx >> 12) & 63;
    int b  = idx >> 18;
    int g0 = hh >> 1, ii = hh & 1, g1 = ww >> 4, jj = ww & 15;
    const float* dp = g_d + (size_t)(b * 256 + g1) * 2048 + g0;
    float acc = wb[0];
    #pragma unroll 8
    for (int c = 0; c < 64; c++)
        acc = fmaf(dp[c * 32], sW[c * 32 + ii * 16 + jj], acc);
    out[idx] = acc;
}

// ---------------------------------------------------------------------------
extern "C" void kernel_launch(void* const* d_in, const int* in_sizes, int n_in,
                              void* d_out, int out_size) {
    const float* x          = (const float*)d_in[0];
    const void*  mk         = d_in[1];
    const float* proj_w     = (const float*)d_in[2];
    const float* proj_b     = (const float*)d_in[3];
    const float* pos_embed  = (const float*)d_in[4];
    const float* in_proj_w  = (const float*)d_in[5];
    const float* conv_w     = (const float*)d_in[6];
    const float* conv_b     = (const float*)d_in[7];
    const float* x_proj_w   = (const float*)d_in[8];
    const float* dt_proj_w  = (const float*)d_in[9];
    const float* dt_proj_b  = (const float*)d_in[10];
    const float* A_log      = (const float*)d_in[11];
    const float* Dp         = (const float*)d_in[12];
    const float* out_proj_w = (const float*)d_in[13];
    const float* ln_g       = (const float*)d_in[14];
    const float* ln_b       = (const float*)d_in[15];
    const float* dec_conv_w = (const float*)d_in[16];
    const float* convT_w    = (const float*)d_in[17];
    const float* convT_b    = (const float*)d_in[18];
    float* out = (float*)d_out;

    float *p_xz, *p_xdbl, *p_dt, *p_o;
    bf16 *p_hhi, *p_hlo, *p_uhi, *p_ulo, *p_xdhi, *p_xdlo, *p_yhi, *p_ylo;
    bf16 *p_inwhi, *p_inwlo, *p_outwhi, *p_outwlo, *p_xwhi, *p_xwlo, *p_dtwhi, *p_dtwlo;
    cudaGetSymbolAddress((void**)&p_hhi,    g_hhi);
    cudaGetSymbolAddress((void**)&p_hlo,    g_hlo);
    cudaGetSymbolAddress((void**)&p_xz,     g_xz);
    cudaGetSymbolAddress((void**)&p_uhi,    g_uhi);
    cudaGetSymbolAddress((void**)&p_ulo,    g_ulo);
    cudaGetSymbolAddress((void**)&p_xdbl,   g_xdbl);
    cudaGetSymbolAddress((void**)&p_xdhi,   g_xdhi);
    cudaGetSymbolAddress((void**)&p_xdlo,   g_xdlo);
    cudaGetSymbolAddress((void**)&p_dt,     g_dt);
    cudaGetSymbolAddress((void**)&p_yhi,    g_yhi);
    cudaGetSymbolAddress((void**)&p_ylo,    g_ylo);
    cudaGetSymbolAddress((void**)&p_o,      g_o);
    cudaGetSymbolAddress((void**)&p_inwhi,  g_inwhi);
    cudaGetSymbolAddress((void**)&p_inwlo,  g_inwlo);
    cudaGetSymbolAddress((void**)&p_outwhi, g_outwhi);
    cudaGetSymbolAddress((void**)&p_outwlo, g_outwlo);
    cudaGetSymbolAddress((void**)&p_xwhi,   g_xwhi);
    cudaGetSymbolAddress((void**)&p_xwlo,   g_xwlo);
    cudaGetSymbolAddress((void**)&p_dtwhi,  g_dtwhi);
    cudaGetSymbolAddress((void**)&p_dtwlo,  g_dtwlo);

    const int TG_SMEM = NSTG * STAGE_B;
    cudaFuncSetAttribute(tgemm<0>, cudaFuncAttributeMaxDynamicSharedMemorySize, TG_SMEM);
    cudaFuncSetAttribute(tgemm<1>, cudaFuncAttributeMaxDynamicSharedMemorySize, TG_SMEM);
    const int BIGK = 1 << 30;

    // 0) mask normalize + weight splits
    mask_detect_kernel<<<1, 256>>>((const unsigned char*)mk);
    mask_norm_kernel<<<NMASK / 256, 256>>>(mk);
    split_kernel<<<4096, 256>>>(in_proj_w, p_inwhi, p_inwlo, XZW * DM);
    split_kernel<<<4096, 256>>>(out_proj_w, p_outwhi, p_outwlo, 2 * DM * DIN);
    split_kernel<<<512, 256>>>(dt_proj_w, p_dtwhi, p_dtwlo, 2 * DIN * DTR);
    padsplit_xw_kernel<<<2 * 256 * DIN / 256, 256>>>(x_proj_w);

    // 1) patch embed + pos embed -> g_h (+hi/lo)
    patch_kernel<<<dim3(256, 8), 256>>>(x, proj_w, proj_b, pos_embed);

    // 2) in_proj (both dirs fused): [2048,2048] @ [16384,2048]^T -> g_xz
    tgemm<0><<<dim3(TOKS / 128, XZW / 128), 256, TG_SMEM>>>(
        p_hhi, p_hlo, DM, BIGK, 0,
        p_inwhi, p_inwlo, DM, BIGK, 0,
        p_xz, XZW, DM, nullptr);

    // 3) depthwise conv + silu -> u (+hi/lo)
    conv_silu_kernel<<<dim3(16, 8, 2), 256>>>(conv_w, conv_b);

    // 4) x_proj (N padded to 256) and dt_proj, tensor path
    for (int dir = 0; dir < 2; dir++) {
        tgemm<0><<<dim3(TOKS / 128, 2), 256, TG_SMEM>>>(
            p_uhi + (size_t)dir * TOKS * DIN, p_ulo + (size_t)dir * TOKS * DIN, DIN,
            BIGK, 0,
            p_xwhi + (size_t)dir * 256 * DIN, p_xwlo + (size_t)dir * 256 * DIN, DIN,
            BIGK, 0,
            p_xdbl + (size_t)dir * TOKS * XDP, XDP, DIN, nullptr);
    }
    split_xd_kernel<<<2 * TOKS * DTR / 256, 256>>>();
    for (int dir = 0; dir < 2; dir++) {
        tgemm<1><<<dim3(TOKS / 128, DIN / 128), 256, TG_SMEM>>>(
            p_xdhi + (size_t)dir * TOKS * DTR, p_xdlo + (size_t)dir * TOKS * DTR, DTR,
            BIGK, 0,
            p_dtwhi + (size_t)dir * DIN * DTR, p_dtwlo + (size_t)dir * DIN * DTR, DTR,
            BIGK, 0,
            p_dt + (size_t)dir * TOKS * DIN, DIN, DTR, dt_proj_b + dir * DIN);
    }

    // 5) selective scan + gating -> y hi/lo (bf16)
    scan_kernel<<<dim3(16, 8, 2), 256>>>(A_log, Dp);

    // 6) out_proj, both dirs fused along K=8192: o = [y0|y1] @ [W0|W1]^T
    tgemm<0><<<dim3(TOKS / 128, DM / 128), 256, TG_SMEM>>>(
        p_yhi, p_ylo, DIN, DIN, (size_t)TOKS * DIN,
        p_outwhi, p_outwlo, DIN, DIN, (size_t)DM * DIN,
        p_o, DM, 2 * DIN, nullptr);

    // 7) residual + LayerNorm
    addln_kernel<<<TOKS, 256>>>(ln_g, ln_b);

    // 8) 31x31 decoder conv
    decconv_kernel<<<dim3(64, 8, 8), 256>>>(dec_conv_w);

    // 9) convT reconstruction
    rec_kernel<<<8192, 256>>>(convT_w, convT_b, out);

    // 10) pass-through x
    if (out_size >= 2 * 2097152) {
        cudaMemcpyAsync(out + 2097152, x, (size_t)2097152 * sizeof(float),
                        cudaMemcpyDeviceToDevice, 0);
    }
}

// round 8
// speedup vs baseline: 2.3194x; 1.1604x over previous
#include <cuda_runtime.h>
#include <cuda_bf16.h>
#include <math.h>
#include <stdint.h>

// ---------------------------------------------------------------------------
// FEMBA forward. All GEMMs on mma.sync bf16 with 2-way split (3 products).
// R7 (resubmit after infra failure): register-blocked decconv, barrier-free
// scan, dir-parallel x/dt GEMMs, x_proj epilogue fuses hi/lo split + BC.
// ---------------------------------------------------------------------------

#define TOKS 2048
#define LSEQ 256
#define DM   2048
#define DIN  4096
#define DS   16
#define DTR  128
#define XZW  16384
#define NMASK (8 * 64 * 4096)

typedef __nv_bfloat16 bf16;

// ---------------- scratch (device globals) ----------------------------------
__device__ float g_h   [TOKS * DM];
__device__ bf16  g_hhi [TOKS * DM];
__device__ bf16  g_hlo [TOKS * DM];
__device__ float g_h2  [TOKS * DM];
__device__ float g_xz  [(size_t)TOKS * XZW];
__device__ bf16  g_uhi [2][TOKS * DIN];
__device__ bf16  g_ulo [2][TOKS * DIN];
__device__ bf16  g_xdhi[2][TOKS * DTR];
__device__ bf16  g_xdlo[2][TOKS * DTR];
__device__ float g_bc  [2][TOKS * 32];
__device__ float g_dt  [2][TOKS * DIN];
__device__ bf16  g_yhi [2][TOKS * DIN];
__device__ bf16  g_ylo [2][TOKS * DIN];
__device__ float g_o   [TOKS * DM];
__device__ float g_d   [TOKS * DM];
__device__ bf16  g_inwhi[(size_t)XZW * DM];
__device__ bf16  g_inwlo[(size_t)XZW * DM];
__device__ bf16  g_outwhi[(size_t)2 * DM * DIN];
__device__ bf16  g_outwlo[(size_t)2 * DM * DIN];
__device__ bf16  g_xwhi[(size_t)2 * 256 * DIN];   // x_proj_w padded 160->256
__device__ bf16  g_xwlo[(size_t)2 * 256 * DIN];
__device__ bf16  g_dtwhi[(size_t)2 * DIN * DTR];
__device__ bf16  g_dtwlo[(size_t)2 * DIN * DTR];
__device__ unsigned char g_mask[NMASK];
__device__ int g_mask_mode;

__device__ __forceinline__ float siluf(float x) { return x / (1.f + __expf(-x)); }

__device__ __forceinline__ uint32_t smem_u32(const void* p) {
    uint32_t a;
    asm("{ .reg .u64 t; cvta.to.shared.u64 t, %1; cvt.u32.u64 %0, t; }" : "=r"(a) : "l"(p));
    return a;
}
__device__ __forceinline__ void cpa16(uint32_t dst, const void* src) {
    asm volatile("cp.async.cg.shared.global [%0], [%1], 16;" :: "r"(dst), "l"(src));
}
__device__ __forceinline__ void ldsm4(uint32_t addr, uint32_t* r) {
    asm volatile("ldmatrix.sync.aligned.m8n8.x4.shared.b16 {%0,%1,%2,%3}, [%4];"
                 : "=r"(r[0]), "=r"(r[1]), "=r"(r[2]), "=r"(r[3]) : "r"(addr));
}
__device__ __forceinline__ void mma_bf16(float* c, const uint32_t* a,
                                         uint32_t b0, uint32_t b1) {
    asm volatile("mma.sync.aligned.m16n8k16.row.col.f32.bf16.bf16.f32 "
                 "{%0,%1,%2,%3}, {%4,%5,%6,%7}, {%8,%9}, {%0,%1,%2,%3};"
                 : "+f"(c[0]), "+f"(c[1]), "+f"(c[2]), "+f"(c[3])
                 : "r"(a[0]), "r"(a[1]), "r"(a[2]), "r"(a[3]), "r"(b0), "r"(b1));
}

// ---------------- 0) mask dtype sniff + normalize ---------------------------
__global__ void mask_detect_kernel(const unsigned char* __restrict__ m) {
    __shared__ int cnt;
    if (threadIdx.x == 0) cnt = 0;
    __syncthreads();
    int local = 0;
    for (int i = threadIdx.x * 4 + 1; i < 65536; i += 1024)
        if (m[i]) local++;
    atomicAdd(&cnt, local);
    __syncthreads();
    if (threadIdx.x == 0) g_mask_mode = (cnt > 0) ? 0 : 1;
}
__global__ void mask_norm_kernel(const void* __restrict__ m) {
    int i = blockIdx.x * 256 + threadIdx.x;
    if (i >= NMASK) return;
    if (g_mask_mode == 0) g_mask[i] = ((const unsigned char*)m)[i] ? 1 : 0;
    else                  g_mask[i] = (((const unsigned int*)m)[i] != 0u) ? 1 : 0;
}

// ---------------- splits -----------------------------------------------------
__global__ void split_kernel(const float* __restrict__ src, bf16* __restrict__ hi,
                             bf16* __restrict__ lo, int n) {
    for (int i = blockIdx.x * 256 + threadIdx.x; i < n; i += gridDim.x * 256) {
        float a = src[i];
        bf16 h = __float2bfloat16_rn(a);
        hi[i] = h;
        lo[i] = __float2bfloat16_rn(a - __bfloat162float(h));
    }
}
// x_proj_w [2,160,4096] -> padded [2,256,4096] hi/lo (rows >=160 zero)
__global__ void padsplit_xw_kernel(const float* __restrict__ src) {
    int i = blockIdx.x * 256 + threadIdx.x;
    int c = i & 4095;
    int r = (i >> 12) & 255;
    int dir = i >> 20;
    float a = (r < 160) ? src[(size_t)(dir * 160 + r) * 4096 + c] : 0.f;
    bf16 h = __float2bfloat16_rn(a);
    g_xwhi[i] = h;
    g_xwlo[i] = __float2bfloat16_rn(a - __bfloat162float(h));
}

// ---------------- 1) patch embed + pos embed --------------------------------
__global__ void patch_kernel(const float* __restrict__ x,
                             const float* __restrict__ pw,
                             const float* __restrict__ pb,
                             const float* __restrict__ pos) {
    int g1 = blockIdx.x, b = blockIdx.y, tid = threadIdx.x;
    __shared__ float sIn[64 * 16];
    __shared__ float sW [64 * 32];
    for (int i = tid; i < 1024; i += 256) {
        int r = i >> 4, c = i & 15;
        size_t gi = (size_t)b * 64 * 4096 + (size_t)r * 4096 + g1 * 16 + c;
        float v = x[gi];
        if (g_mask[gi]) v = 0.f;
        sIn[i] = v;
    }
    for (int i = tid; i < 2048; i += 256) sW[i] = pw[i];
    __syncthreads();
    size_t ob = (size_t)(b * 256 + g1) * 2048;
    #pragma unroll
    for (int rep = 0; rep < 8; rep++) {
        int ch = tid + rep * 256;
        int e = ch >> 5, g0 = ch & 31;
        float acc = pb[e] + pos[g1 * 2048 + ch];
        const float* w   = &sW[e * 32];
        const float* in0 = &sIn[(2 * g0) * 16];
        #pragma unroll
        for (int j = 0; j < 32; j++) acc = fmaf(in0[j], w[j], acc);
        g_h[ob + ch] = acc;
        bf16 hv = __float2bfloat16_rn(acc);
        g_hhi[ob + ch] = hv;
        g_hlo[ob + ch] = __float2bfloat16_rn(acc - __bfloat162float(hv));
    }
}

// ---------------- mma.sync bf16x3 GEMM: C[M,N] = A[M,K] @ B[N,K]^T ----------
// CTA tile 128x128, K-chunk 32, 3-stage cp.async ring.
// blockIdx.z selects a "dir": A/B/C/bias shifted by per-dir strides.
// EPI: 0 = store, 1 = softplus(acc + bias[col]), 2 = xdbl epilogue
// (cols<128 -> bf16 hi/lo into g_xd*, 128..159 -> fp32 into g_bc, rest drop).
#define HALF_B  10240
#define STAGE_B 40960
#define NSTG    3

__device__ __forceinline__ void xd_store(int dir, int row, int col,
                                         float v0, float v1) {
    if (col < 128) {
        bf16 h0 = __float2bfloat16_rn(v0);
        bf16 h1 = __float2bfloat16_rn(v1);
        g_xdhi[dir][row * DTR + col]     = h0;
        g_xdhi[dir][row * DTR + col + 1] = h1;
        g_xdlo[dir][row * DTR + col]     = __float2bfloat16_rn(v0 - __bfloat162float(h0));
        g_xdlo[dir][row * DTR + col + 1] = __float2bfloat16_rn(v1 - __bfloat162float(h1));
    } else if (col < 160) {
        g_bc[dir][row * 32 + col - 128] = v0;
        g_bc[dir][row * 32 + col - 127] = v1;
    }
}

template <int EPI>
__global__ void __launch_bounds__(256)
tgemm(const bf16* __restrict__ Ah, const bf16* __restrict__ Al, int lda,
      int aKsplit, size_t aDirStride, size_t aZ,
      const bf16* __restrict__ Bh, const bf16* __restrict__ Bl, int ldb,
      int bKsplit, size_t bDirStride, size_t bZ,
      float* __restrict__ C, int ldc, size_t cZ, int K,
      const float* __restrict__ bias, size_t biasZ) {
    extern __shared__ char smem[];
    uint32_t sb = smem_u32(smem);
    int tid = threadIdx.x, lane = tid & 31, wid = tid >> 5;
    int bm = blockIdx.x * 128, bn = blockIdx.y * 128;
    int zz = blockIdx.z;
    int wm = (wid >> 2) * 64, wn = (wid & 3) * 32;

    Ah += (size_t)zz * aZ; Al += (size_t)zz * aZ;
    Bh += (size_t)zz * bZ; Bl += (size_t)zz * bZ;
    if (EPI != 2) C += (size_t)zz * cZ;
    if (EPI == 1) bias += (size_t)zz * biasZ;

    float acc[4][4][4] = {};
    int NK = K / 32;

    auto load = [&](int chunk) {
        int k0 = chunk * 32;
        size_t aoff = (k0 < aKsplit) ? (size_t)k0 : aDirStride + (size_t)(k0 - aKsplit);
        size_t boff = (k0 < bKsplit) ? (size_t)k0 : bDirStride + (size_t)(k0 - bKsplit);
        uint32_t st = sb + (chunk % NSTG) * STAGE_B;
        #pragma unroll
        for (int i = 0; i < 2; i++) {
            int idx = tid * 2 + i;
            int row = idx >> 2, c = idx & 3;
            uint32_t d = st + row * 80 + c * 16;
            size_t ga = (size_t)(bm + row) * lda + aoff + c * 8;
            size_t gb = (size_t)(bn + row) * ldb + boff + c * 8;
            cpa16(d,              Ah + ga);
            cpa16(d + HALF_B,     Al + ga);
            cpa16(d + 2 * HALF_B, Bh + gb);
            cpa16(d + 3 * HALF_B, Bl + gb);
        }
        asm volatile("cp.async.commit_group;" ::: "memory");
    };

    load(0);
    if (NK > 1) load(1);

    for (int i = 0; i < NK; i++) {
        if (i + 1 < NK) asm volatile("cp.async.wait_group 1;" ::: "memory");
        else            asm volatile("cp.async.wait_group 0;" ::: "memory");
        __syncthreads();
        if (i + 2 < NK) load(i + 2);
        uint32_t st = sb + (i % NSTG) * STAGE_B;
        #pragma unroll
        for (int s = 0; s < 2; s++) {
            int kb = s * 32;
            uint32_t ah[4][4], al[4][4], bh[2][4], bl[2][4];
            int arow = wm + (lane & 7) + ((lane & 8) ? 8 : 0);
            int acol = ((lane & 16) ? 16 : 0) + kb;
            #pragma unroll
            for (int mt = 0; mt < 4; mt++) {
                uint32_t ad = st + (arow + mt * 16) * 80 + acol;
                ldsm4(ad, ah[mt]);
                ldsm4(ad + HALF_B, al[mt]);
            }
            int brow = wn + (lane & 7) + ((lane & 16) ? 8 : 0);
            int bcol = ((lane & 8) ? 16 : 0) + kb;
            #pragma unroll
            for (int bt = 0; bt < 2; bt++) {
                uint32_t bd = st + 2 * HALF_B + (brow + bt * 16) * 80 + bcol;
                ldsm4(bd, bh[bt]);
                ldsm4(bd + HALF_B, bl[bt]);
            }
            #pragma unroll
            for (int mt = 0; mt < 4; mt++)
                #pragma unroll
                for (int nt = 0; nt < 4; nt++) {
                    uint32_t h0 = bh[nt >> 1][(nt & 1) * 2];
                    uint32_t h1 = bh[nt >> 1][(nt & 1) * 2 + 1];
                    uint32_t l0 = bl[nt >> 1][(nt & 1) * 2];
                    uint32_t l1 = bl[nt >> 1][(nt & 1) * 2 + 1];
                    mma_bf16(acc[mt][nt], ah[mt], h0, h1);
                    mma_bf16(acc[mt][nt], ah[mt], l0, l1);
                    mma_bf16(acc[mt][nt], al[mt], h0, h1);
                }
        }
        __syncthreads();
    }

    #pragma unroll
    for (int mt = 0; mt < 4; mt++) {
        int r0 = bm + wm + mt * 16 + (lane >> 2);
        #pragma unroll
        for (int nt = 0; nt < 4; nt++) {
            int col = bn + wn + nt * 8 + (lane & 3) * 2;
            float v0 = acc[mt][nt][0], v1 = acc[mt][nt][1];
            float v2 = acc[mt][nt][2], v3 = acc[mt][nt][3];
            if (EPI == 2) {
                xd_store(zz, r0, col, v0, v1);
                xd_store(zz, r0 + 8, col, v2, v3);
            } else {
                if (EPI == 1) {
                    float b0 = bias[col], b1 = bias[col + 1];
                    v0 += b0; v1 += b1; v2 += b0; v3 += b1;
                    v0 = (v0 > 20.f) ? v0 : log1pf(expf(v0));
                    v1 = (v1 > 20.f) ? v1 : log1pf(expf(v1));
                    v2 = (v2 > 20.f) ? v2 : log1pf(expf(v2));
                    v3 = (v3 > 20.f) ? v3 : log1pf(expf(v3));
                }
                *(float2*)&C[(size_t)r0 * ldc + col] = make_float2(v0, v1);
                *(float2*)&C[(size_t)(r0 + 8) * ldc + col] = make_float2(v2, v3);
            }
        }
    }
}

// ---------------- 2) depthwise conv + silu (emits u hi/lo bf16) -------------
__global__ void conv_silu_kernel(const float* __restrict__ cw,
                                 const float* __restrict__ cb) {
    int d = blockIdx.x * 256 + threadIdx.x;
    int b = blockIdx.y, dir = blockIdx.z;
    float w0 = cw[(dir * DIN + d) * 4 + 0];
    float w1 = cw[(dir * DIN + d) * 4 + 1];
    float w2 = cw[(dir * DIN + d) * 4 + 2];
    float w3 = cw[(dir * DIN + d) * 4 + 3];
    float bias = cb[dir * DIN + d];
    const float* src = g_xz + (size_t)(b * LSEQ) * XZW + dir * 8192 + d;
    bf16* dh = g_uhi[dir] + (size_t)(b * LSEQ) * DIN + d;
    bf16* dl = g_ulo[dir] + (size_t)(b * LSEQ) * DIN + d;
    float x1 = 0.f, x2 = 0.f, x3 = 0.f;
    if (dir == 0) {
        for (int l = 0; l < LSEQ; l++) {
            float x0 = src[(size_t)l * XZW];
            float v = siluf(bias + w0 * x3 + w1 * x2 + w2 * x1 + w3 * x0);
            bf16 hv = __float2bfloat16_rn(v);
            dh[(size_t)l * DIN] = hv;
            dl[(size_t)l * DIN] = __float2bfloat16_rn(v - __bfloat162float(hv));
            x3 = x2; x2 = x1; x1 = x0;
        }
    } else {
        for (int l = LSEQ - 1; l >= 0; l--) {
            float x0 = src[(size_t)l * XZW];
            float v = siluf(bias + w3 * x0 + w2 * x1 + w1 * x2 + w0 * x3);
            bf16 hv = __float2bfloat16_rn(v);
            dh[(size_t)l * DIN] = hv;
            dl[(size_t)l * DIN] = __float2bfloat16_rn(v - __bfloat162float(hv));
            x3 = x2; x2 = x1; x1 = x0;
        }
    }
}

// ---------------- 3) selective scan + gating (barrier-free) -----------------
__global__ void scan_kernel(const float* __restrict__ A_log,
                            const float* __restrict__ Dp) {
    int d = blockIdx.x * 256 + threadIdx.x;
    int b = blockIdx.y, dir = blockIdx.z;
    __shared__ float sBC[LSEQ * 32];   // all B/C for this (b,dir): 32 KB
    const float* bcsrc = g_bc[dir] + (size_t)b * LSEQ * 32;
    for (int i = threadIdx.x; i < LSEQ * 32; i += 256) sBC[i] = bcsrc[i];

    float Aa[16];
    #pragma unroll
    for (int s = 0; s < 16; s++)
        Aa[s] = -expf(A_log[(size_t)(dir * DIN + d) * 16 + s]);
    float dpv = Dp[dir * DIN + d];
    const float* dtp = g_dt[dir] + d;
    const bf16* uhp  = g_uhi[dir] + d;
    const bf16* ulp  = g_ulo[dir] + d;
    const float* zp  = g_xz + (size_t)dir * 8192 + 4096 + d;
    bf16* yh = g_yhi[dir] + d;
    bf16* yl = g_ylo[dir] + d;
    float st[16];
    #pragma unroll
    for (int s = 0; s < 16; s++) st[s] = 0.f;
    __syncthreads();
    for (int step = 0; step < LSEQ; step++) {
        int l = dir ? (LSEQ - 1 - step) : step;
        size_t t = (size_t)b * LSEQ + l;
        float dtv = dtp[t * DIN];
        float uv  = __bfloat162float(uhp[t * DIN]) + __bfloat162float(ulp[t * DIN]);
        float zv  = zp[t * XZW];
        const float* bcl = &sBC[l * 32];
        float du  = dtv * uv;
        float accv = 0.f;
        #pragma unroll
        for (int s = 0; s < 16; s++) {
            float dA = __expf(dtv * Aa[s]);
            st[s] = fmaf(st[s], dA, du * bcl[s]);
            accv = fmaf(st[s], bcl[16 + s], accv);
        }
        float yv = (accv + uv * dpv) * siluf(zv);
        bf16 hv = __float2bfloat16_rn(yv);
        yh[t * DIN] = hv;
        yl[t * DIN] = __float2bfloat16_rn(yv - __bfloat162float(hv));
    }
}

// ---------------- 4) residual add + LayerNorm -------------------------------
__global__ void addln_kernel(const float* __restrict__ g,
                             const float* __restrict__ be) {
    int t = blockIdx.x, tid = threadIdx.x;
    size_t base = (size_t)t * DM;
    float v[8], s = 0.f, s2 = 0.f;
    #pragma unroll
    for (int i = 0; i < 8; i++) {
        int idx = tid + i * 256;
        float val = g_h[base + idx] + g_o[base + idx];
        v[i] = val; s += val; s2 += val * val;
    }
    __shared__ float rs[8], rs2[8];
    #pragma unroll
    for (int off = 16; off; off >>= 1) {
        s  += __shfl_xor_sync(0xffffffffu, s,  off);
        s2 += __shfl_xor_sync(0xffffffffu, s2, off);
    }
    if ((tid & 31) == 0) { rs[tid >> 5] = s; rs2[tid >> 5] = s2; }
    __syncthreads();
    float S = 0.f, S2 = 0.f;
    #pragma unroll
    for (int i = 0; i < 8; i++) { S += rs[i]; S2 += rs2[i]; }
    float mean = S * (1.f / 2048.f);
    float var  = S2 * (1.f / 2048.f) - mean * mean;
    float rinv = rsqrtf(var + 1e-5f);
    #pragma unroll
    for (int i = 0; i < 8; i++) {
        int idx = tid + i * 256;
        g_h2[base + idx] = (v[i] - mean) * rinv * g[idx] + be[idx];
    }
}

// ---------------- 5) 31x31 SAME conv, register-blocked 4 cols/thread --------
__global__ void decconv_kernel(const float* __restrict__ kw) {
    __shared__ float sIn[62 * 63];   // pitch 63: conflict-free window loads
    __shared__ float sW[961];
    int w0 = blockIdx.x * 32, h0 = blockIdx.y * 32, b = blockIdx.z;
    int tid = threadIdx.x;
    for (int i = tid; i < 62 * 62; i += 256) {
        int r = i / 62, c = i % 62;
        int gh = h0 - 15 + r, gw = w0 - 15 + c;
        float v = 0.f;
        if (gh >= 0 && gh < 256 && gw >= 0 && gw < 2048)
            v = g_h2[(size_t)(b * 256 + gh) * 2048 + gw];
        sIn[r * 63 + c] = v;
    }
    for (int i = tid; i < 961; i += 256) sW[i] = kw[i];
    __syncthreads();
    int tx = (tid & 7) * 4, ty = tid >> 3;    // 8 col-groups x 32 rows
    float a0 = 0.f, a1 = 0.f, a2 = 0.f, a3 = 0.f;
    for (int ky = 0; ky < 31; ky++) {
        const float* r = &sIn[(ty + ky) * 63 + tx];
        float win[34];
        #pragma unroll
        for (int j = 0; j < 34; j++) win[j] = r[j];
        const float* wr = &sW[ky * 31];
        #pragma unroll
        for (int kx = 0; kx < 31; kx++) {
            float w = wr[kx];
            a0 = fmaf(win[kx],     w, a0);
            a1 = fmaf(win[kx + 1], w, a1);
            a2 = fmaf(win[kx + 2], w, a2);
            a3 = fmaf(win[kx + 3], w, a3);
        }
    }
    *(float4*)&g_d[(size_t)(b * 256 + h0 + ty) * 2048 + w0 + tx] =
        make_float4(a0, a1, a2, a3);
}

// ---------------- 6) convT reconstruction -----------------------------------
__global__ void rec_kernel(const float* __restrict__ wt,
                           const float* __restrict__ wb,
                           float* __restrict__ out) {
    __shared__ float sW[2048];
    for (int i = threadIdx.x; i < 2048; i += 256) sW[i] = wt[i];
    __syncthreads();
    int idx = blockIdx.x * 256 + threadIdx.x;
    int ww = idx & 4095;
    int hh = (idx >> 12) & 63;
    int b  = idx >> 18;
    int g0 = hh >> 1, ii = hh & 1, g1 = ww >> 4, jj = ww & 15;
    const float* dp = g_d + (size_t)(b * 256 + g1) * 2048 + g0;
    float acc = wb[0];
    #pragma unroll 8
    for (int c = 0; c < 64; c++)
        acc = fmaf(dp[c * 32], sW[c * 32 + ii * 16 + jj], acc);
    out[idx] = acc;
}

// ---------------------------------------------------------------------------
extern "C" void kernel_launch(void* const* d_in, const int* in_sizes, int n_in,
                              void* d_out, int out_size) {
    const float* x          = (const float*)d_in[0];
    const void*  mk         = d_in[1];
    const float* proj_w     = (const float*)d_in[2];
    const float* proj_b     = (const float*)d_in[3];
    const float* pos_embed  = (const float*)d_in[4];
    const float* in_proj_w  = (const float*)d_in[5];
    const float* conv_w     = (const float*)d_in[6];
    const float* conv_b     = (const float*)d_in[7];
    const float* x_proj_w   = (const float*)d_in[8];
    const float* dt_proj_w  = (const float*)d_in[9];
    const float* dt_proj_b  = (const float*)d_in[10];
    const float* A_log      = (const float*)d_in[11];
    const float* Dp         = (const float*)d_in[12];
    const float* out_proj_w = (const float*)d_in[13];
    const float* ln_g       = (const float*)d_in[14];
    const float* ln_b       = (const float*)d_in[15];
    const float* dec_conv_w = (const float*)d_in[16];
    const float* convT_w    = (const float*)d_in[17];
    const float* convT_b    = (const float*)d_in[18];
    float* out = (float*)d_out;

    float *p_xz, *p_dt, *p_o;
    bf16 *p_hhi, *p_hlo, *p_uhi, *p_ulo, *p_xdhi, *p_xdlo, *p_yhi, *p_ylo;
    bf16 *p_inwhi, *p_inwlo, *p_outwhi, *p_outwlo, *p_xwhi, *p_xwlo, *p_dtwhi, *p_dtwlo;
    cudaGetSymbolAddress((void**)&p_hhi,    g_hhi);
    cudaGetSymbolAddress((void**)&p_hlo,    g_hlo);
    cudaGetSymbolAddress((void**)&p_xz,     g_xz);
    cudaGetSymbolAddress((void**)&p_uhi,    g_uhi);
    cudaGetSymbolAddress((void**)&p_ulo,    g_ulo);
    cudaGetSymbolAddress((void**)&p_xdhi,   g_xdhi);
    cudaGetSymbolAddress((void**)&p_xdlo,   g_xdlo);
    cudaGetSymbolAddress((void**)&p_dt,     g_dt);
    cudaGetSymbolAddress((void**)&p_yhi,    g_yhi);
    cudaGetSymbolAddress((void**)&p_ylo,    g_ylo);
    cudaGetSymbolAddress((void**)&p_o,      g_o);
    cudaGetSymbolAddress((void**)&p_inwhi,  g_inwhi);
    cudaGetSymbolAddress((void**)&p_inwlo,  g_inwlo);
    cudaGetSymbolAddress((void**)&p_outwhi, g_outwhi);
    cudaGetSymbolAddress((void**)&p_outwlo, g_outwlo);
    cudaGetSymbolAddress((void**)&p_xwhi,   g_xwhi);
    cudaGetSymbolAddress((void**)&p_xwlo,   g_xwlo);
    cudaGetSymbolAddress((void**)&p_dtwhi,  g_dtwhi);
    cudaGetSymbolAddress((void**)&p_dtwlo,  g_dtwlo);

    const int TG_SMEM = NSTG * STAGE_B;
    cudaFuncSetAttribute(tgemm<0>, cudaFuncAttributeMaxDynamicSharedMemorySize, TG_SMEM);
    cudaFuncSetAttribute(tgemm<1>, cudaFuncAttributeMaxDynamicSharedMemorySize, TG_SMEM);
    cudaFuncSetAttribute(tgemm<2>, cudaFuncAttributeMaxDynamicSharedMemorySize, TG_SMEM);
    const int BIGK = 1 << 30;

    // 0) mask normalize + weight splits
    mask_detect_kernel<<<1, 256>>>((const unsigned char*)mk);
    mask_norm_kernel<<<NMASK / 256, 256>>>(mk);
    split_kernel<<<4096, 256>>>(in_proj_w, p_inwhi, p_inwlo, XZW * DM);
    split_kernel<<<4096, 256>>>(out_proj_w, p_outwhi, p_outwlo, 2 * DM * DIN);
    split_kernel<<<512, 256>>>(dt_proj_w, p_dtwhi, p_dtwlo, 2 * DIN * DTR);
    padsplit_xw_kernel<<<2 * 256 * DIN / 256, 256>>>(x_proj_w);

    // 1) patch embed + pos embed -> g_h (+hi/lo)
    patch_kernel<<<dim3(256, 8), 256>>>(x, proj_w, proj_b, pos_embed);

    // 2) in_proj (both dirs fused): [2048,2048] @ [16384,2048]^T -> g_xz
    tgemm<0><<<dim3(TOKS / 128, XZW / 128, 1), 256, TG_SMEM>>>(
        p_hhi, p_hlo, DM, BIGK, 0, 0,
        p_inwhi, p_inwlo, DM, BIGK, 0, 0,
        p_xz, XZW, 0, DM, nullptr, 0);

    // 3) depthwise conv + silu -> u hi/lo
    conv_silu_kernel<<<dim3(16, 8, 2), 256>>>(conv_w, conv_b);

    // 4a) x_proj, both dirs in one launch; epilogue emits xd hi/lo + BC
    tgemm<2><<<dim3(TOKS / 128, 2, 2), 256, TG_SMEM>>>(
        p_uhi, p_ulo, DIN, BIGK, 0, (size_t)TOKS * DIN,
        p_xwhi, p_xwlo, DIN, BIGK, 0, (size_t)256 * DIN,
        nullptr, 0, 0, DIN, nullptr, 0);

    // 4b) dt_proj, both dirs in one launch, softplus+bias epilogue
    tgemm<1><<<dim3(TOKS / 128, DIN / 128, 2), 256, TG_SMEM>>>(
        p_xdhi, p_xdlo, DTR, BIGK, 0, (size_t)TOKS * DTR,
        p_dtwhi, p_dtwlo, DTR, BIGK, 0, (size_t)DIN * DTR,
        p_dt, DIN, (size_t)TOKS * DIN, DTR, dt_proj_b, DIN);

    // 5) selective scan + gating -> y hi/lo (bf16)
    scan_kernel<<<dim3(16, 8, 2), 256>>>(A_log, Dp);

    // 6) out_proj, both dirs fused along K=8192: o = [y0|y1] @ [W0|W1]^T
    tgemm<0><<<dim3(TOKS / 128, DM / 128, 1), 256, TG_SMEM>>>(
        p_yhi, p_ylo, DIN, DIN, (size_t)TOKS * DIN, 0,
        p_outwhi, p_outwlo, DIN, DIN, (size_t)DM * DIN, 0,
        p_o, DM, 0, 2 * DIN, nullptr, 0);

    // 7) residual + LayerNorm
    addln_kernel<<<TOKS, 256>>>(ln_g, ln_b);

    // 8) 31x31 decoder conv (register-blocked)
    decconv_kernel<<<dim3(64, 8, 8), 256>>>(dec_conv_w);

    // 9) convT reconstruction
    rec_kernel<<<8192, 256>>>(convT_w, convT_b, out);

    // 10) pass-through x
    if (out_size >= 2 * 2097152) {
        cudaMemcpyAsync(out + 2097152, x, (size_t)2097152 * sizeof(float),
                        cudaMemcpyDeviceToDevice, 0);
    }
}